// round 14
// baseline (speedup 1.0000x reference)
#include <cuda_runtime.h>
#include <math.h>

#define NN   32768
#define DD   128
#define EE   524288
#define BB   64
#define EPSC 1e-5f
#define QS   1048576.0f   // 2^20 fixed-point scale for deterministic BN stats
#define CAPE 4608         // per-CTA csr smem capacity (avg 4096, +8 sigma)

// ---------------- static device scratch (no allocation allowed) ----------------
__device__ float g_raw[NN*DD];
__device__ float g_Z[NN*DD];
__device__ float g_dinv[NN];
__device__ int   g_indeg[NN];      // statically zero; k_scan re-zeroes after read
__device__ int   g_rowoff[NN+1];
__device__ int   g_cursor[NN];
__device__ int2  g_csr[EE];        // (src, bitcast weight), grouped by dst, sorted by src
__device__ unsigned long long g_isum[DD];
__device__ unsigned long long g_isq[DD];
__device__ int   g_done;
__device__ float g_scale[DD];
__device__ float g_shift[DD];
__device__ float g_tgB[BB*DD];

// ---------------- f32x2 helpers (packed fp32, exact numerics) ----------------
typedef unsigned long long u64t;
__device__ __forceinline__ u64t pk2(float lo, float hi){
  u64t r; asm("mov.b64 %0,{%1,%2};" : "=l"(r) : "f"(lo), "f"(hi)); return r;
}
__device__ __forceinline__ void upk2(u64t v, float &lo, float &hi){
  asm("mov.b64 {%0,%1},%2;" : "=f"(lo), "=f"(hi) : "l"(v));
}
__device__ __forceinline__ void fma2(u64t &d, u64t a, u64t b){
  asm("fma.rn.f32x2 %0,%1,%2,%0;" : "+l"(d) : "l"(a), "l"(b));
}

__device__ __forceinline__ void statAdd(unsigned long long* p, float v){
  long long q = __float2ll_rn(v * QS);
  atomicAdd(p, (unsigned long long)q);
}

// ---------------- graph preprocessing ----------------
__global__ void k_count(const int* __restrict__ edst){
  int e = blockIdx.x*256 + threadIdx.x;
  if (e < EE) atomicAdd(&g_indeg[edst[e]], 1);
}

__global__ void k_scan(){
  __shared__ int sm[1024];
  int t = threadIdx.x;
  int base = t*32;
  int v[32]; int tot = 0;
  #pragma unroll
  for (int i=0;i<32;i++){ v[i] = g_indeg[base+i]; tot += v[i]; g_indeg[base+i] = 0; }
  sm[t] = tot;
  __syncthreads();
  for (int off=1; off<1024; off<<=1){
    int x = (t>=off) ? sm[t-off] : 0;
    __syncthreads();
    sm[t] += x;
    __syncthreads();
  }
  int run = sm[t] - tot;
  #pragma unroll
  for (int i=0;i<32;i++){
    g_rowoff[base+i] = run;
    g_cursor[base+i] = run;
    g_dinv[base+i]   = rsqrtf(1.0f + (float)v[i]);
    run += v[i];
  }
  if (t == 1023) g_rowoff[NN] = run;
}

__global__ void k_fill(const int* __restrict__ esrc, const int* __restrict__ edst){
  int e = blockIdx.x*256 + threadIdx.x;
  if (e >= EE) return;
  int s = esrc[e], d = edst[e];
  float w = g_dinv[s]*g_dinv[d];
  int p = atomicAdd(&g_cursor[d], 1);
  g_csr[p] = make_int2(s, __float_as_int(w));
}

// -------- sraw0 v2: warp-per-node rank sort + layer0 + BN0 finalize ----------
__global__ __launch_bounds__(256) void k_sraw0(const float* __restrict__ x,
    const float* __restrict__ W0, const float* __restrict__ b0,
    const float* __restrict__ gm, const float* __restrict__ bt){
  __shared__ int2 rowA[8][64];
  __shared__ int2 rowB[8][64];
  __shared__ float sS[8], sQ[8];
  __shared__ bool isLast;
  int tid = threadIdx.x, w = tid>>5, l = tid&31;
  int n = blockIdx.x*8 + w;
  int r0 = g_rowoff[n], r1 = g_rowoff[n+1];
  int len = r1 - r0;
  float s;
  if (len <= 64){
    if (l < len)      rowA[w][l]      = g_csr[r0 + l];
    if (32 + l < len) rowA[w][32 + l] = g_csr[r0 + 32 + l];
    __syncwarp();
    for (int p = l; p < len; p += 32){
      int2 key = rowA[w][p];
      int rank = 0;
      for (int i = 0; i < len; i++){
        int2 o = rowA[w][i];
        rank += (o.x < key.x) || (o.x == key.x && i < p);
      }
      rowB[w][rank] = key;
      g_csr[r0 + rank] = key;
    }
    __syncwarp();
    float part = 0.f;
    if (l < len){      int2 e = rowB[w][l];      part = __int_as_float(e.y) * x[e.x]; }
    if (32 + l < len){ int2 e = rowB[w][32 + l]; part = fmaf(__int_as_float(e.y), x[e.x], part); }
    #pragma unroll
    for (int off=16; off; off>>=1) part += __shfl_xor_sync(0xffffffffu, part, off);
    float dv = g_dinv[n];
    s = fmaf(dv*dv, x[n], part);
  } else {
    if (l == 0){
      for (int i = r0+1; i < r1; i++){
        int2 key = g_csr[i];
        int j = i-1;
        while (j >= r0 && g_csr[j].x > key.x){ g_csr[j+1] = g_csr[j]; j--; }
        g_csr[j+1] = key;
      }
    }
    __syncwarp();
    float part = 0.f;
    for (int j = r0 + l; j < r1; j += 32){
      int2 e = g_csr[j];
      part = fmaf(__int_as_float(e.y), x[e.x], part);
    }
    #pragma unroll
    for (int off=16; off; off>>=1) part += __shfl_xor_sync(0xffffffffu, part, off);
    float dv = g_dinv[n];
    s = fmaf(dv*dv, x[n], part);
  }
  {
    float4 W4 = *(const float4*)&W0[l*4];
    float4 b4 = *(const float4*)&b0[l*4];
    float4 r;
    r.x = fmaf(s, W4.x, b4.x);
    r.y = fmaf(s, W4.y, b4.y);
    r.z = fmaf(s, W4.z, b4.z);
    r.w = fmaf(s, W4.w, b4.w);
    ((float4*)g_raw)[n*32 + l] = r;
  }
  if (l == 0){ sS[w] = s; sQ[w] = s*s; }
  __syncthreads();
  if (tid == 0){
    float S = 0.f, Q = 0.f;
    #pragma unroll
    for (int q=0;q<8;q++){ S += sS[q]; Q += sQ[q]; }
    statAdd(&g_isum[0], S);
    statAdd(&g_isq[0],  Q);
  }
  __threadfence();
  __syncthreads();
  if (tid == 0) isLast = (atomicAdd(&g_done, 1) == gridDim.x - 1);
  __syncthreads();
  if (isLast){
    if (tid < 128){
      unsigned long long us = atomicAdd(&g_isum[0], 0ull);
      unsigned long long uq = atomicAdd(&g_isq[0],  0ull);
      double S = (double)(long long)us / (double)QS;
      double Q = (double)(long long)uq / (double)QS;
      double mS = S / NN;
      double vS = Q / NN - mS*mS;
      double wv = (double)W0[tid];
      float mean = (float)(wv*mS + (double)b0[tid]);
      float var  = (float)(wv*wv*vS);
      float sc = gm[tid] * rsqrtf(var + EPSC);
      g_scale[tid] = sc;
      g_shift[tid] = bt[tid] - mean*sc;
      g_isum[tid] = 0ull; g_isq[tid] = 0ull;
    }
    if (tid == 0) g_done = 0;
  }
}

// ---------------- GEMM v4 (best known): k-split f32x2 packing -----------------
#define GEMM_SMEM (64*132*4 + 64*128*8)
__global__ __launch_bounds__(256,2) void k_gemm(const float* __restrict__ W){
  extern __shared__ float smem[];
  float (*As)[132] = (float(*)[132])smem;          // [64][132]
  u64t* WT = (u64t*)(smem + 64*132);               // [64][128]
  int tid = threadIdx.x;
  int w = tid>>5, l = tid&31;
  int w8 = w*8;
  #pragma unroll
  for (int i=0;i<8;i++){
    int f = tid + i*256;            // 0..2047
    int kp = f>>5, c4 = f&31;
    float4 wa = ((const float4*)W)[(2*kp)*32 + c4];
    float4 wb = ((const float4*)W)[(2*kp+1)*32 + c4];
    ulonglong2 p0, p1;
    p0.x = pk2(wa.x, wb.x); p0.y = pk2(wa.y, wb.y);
    p1.x = pk2(wa.z, wb.z); p1.y = pk2(wa.w, wb.w);
    *(ulonglong2*)&WT[kp*128 + c4*4]     = p0;
    *(ulonglong2*)&WT[kp*128 + c4*4 + 2] = p1;
  }
  const float4* A4g = (const float4*)g_raw;
  for (int t = blockIdx.x; t < NN/64; t += 296){
    int row0 = t*64;
    __syncthreads();
    #pragma unroll
    for (int i=0;i<8;i++){
      int f = tid + i*256;
      int r = f>>5, k4 = f&31;
      float4 v  = A4g[(row0+r)*32 + k4];
      float4 sc = *(const float4*)&g_scale[k4*4];
      float4 sh = *(const float4*)&g_shift[k4*4];
      float4 h;
      h.x = fmaxf(fmaf(v.x, sc.x, sh.x), 0.f);
      h.y = fmaxf(fmaf(v.y, sc.y, sh.y), 0.f);
      h.z = fmaxf(fmaf(v.z, sc.z, sh.z), 0.f);
      h.w = fmaxf(fmaf(v.w, sc.w, sh.w), 0.f);
      *(float4*)&As[r][k4*4] = h;
    }
    __syncthreads();
    u64t acc[8][4];
    #pragma unroll
    for (int r=0;r<8;r++)
      #pragma unroll
      for (int c=0;c<4;c++) acc[r][c] = 0ull;
    #pragma unroll 4
    for (int kq=0;kq<32;kq++){
      u64t w0 = WT[(2*kq)*128 + l];
      u64t w1 = WT[(2*kq)*128 + 32 + l];
      u64t w2 = WT[(2*kq)*128 + 64 + l];
      u64t w3 = WT[(2*kq)*128 + 96 + l];
      u64t v0 = WT[(2*kq+1)*128 + l];
      u64t v1 = WT[(2*kq+1)*128 + 32 + l];
      u64t v2 = WT[(2*kq+1)*128 + 64 + l];
      u64t v3 = WT[(2*kq+1)*128 + 96 + l];
      #pragma unroll
      for (int r=0;r<8;r++){
        ulonglong2 ar = *(const ulonglong2*)&As[w8+r][kq*4];
        fma2(acc[r][0], ar.x, w0); fma2(acc[r][1], ar.x, w1);
        fma2(acc[r][2], ar.x, w2); fma2(acc[r][3], ar.x, w3);
        fma2(acc[r][0], ar.y, v0); fma2(acc[r][1], ar.y, v1);
        fma2(acc[r][2], ar.y, v2); fma2(acc[r][3], ar.y, v3);
      }
    }
    #pragma unroll
    for (int r=0;r<8;r++){
      int row = row0 + w8 + r;
      float lo, hi;
      upk2(acc[r][0], lo, hi); g_Z[row*128 + l]      = lo + hi;
      upk2(acc[r][1], lo, hi); g_Z[row*128 + 32 + l] = lo + hi;
      upk2(acc[r][2], lo, hi); g_Z[row*128 + 64 + l] = lo + hi;
      upk2(acc[r][3], lo, hi); g_Z[row*128 + 96 + l] = lo + hi;
    }
  }
}

// ------- aggregation v4 + SAFE probe variant (SAFE=1 masks gather indices) -----
#define AGG_SMEM (131072 + CAPE*8 + (258+256)*4)
template<int SAFE>
__global__ __launch_bounds__(1024) void k_agg(const float* __restrict__ bias,
                                              const float* __restrict__ gm,
                                              const float* __restrict__ bt){
  extern __shared__ char smraw[];
  float4* S4  = (float4*)smraw;
  int2*  csrS = (int2*)(smraw + 131072);
  int*   rb   = (int*)(smraw + 131072 + CAPE*8);
  int*   sp   = rb + 258;
  __shared__ bool isLast;
  int c = blockIdx.x, g = c>>1, half = c&1;
  int dstBase = g*512 + half*256;
  int tid = threadIdx.x, w = tid>>5, l = tid&31;
  const float4* Z4 = (const float4*)g_Z;
  float4* R4 = (float4*)g_raw;
  if (tid < 257) rb[tid] = g_rowoff[dstBase + tid];
  int e0 = g_rowoff[dstBase];
  int ecnt = g_rowoff[dstBase + 256] - e0;
  int scnt = ecnt < CAPE ? ecnt : CAPE;
  for (int i = tid; i < scnt; i += 1024) csrS[i] = g_csr[e0 + i];
  __syncthreads();
  if (tid < 256){
    int lo = rb[tid] - e0, hi = rb[tid+1] - e0;
    int cut = (dstBase & ~511) + 256;
    while (lo < hi){
      int mid = (lo + hi) >> 1;
      int2 e = (mid < scnt) ? csrS[mid] : g_csr[e0 + mid];
      if (e.x >= cut) hi = mid; else lo = mid + 1;
    }
    sp[tid] = lo + e0;
  }
  __syncthreads();

  float4 acc[8];
  #pragma unroll
  for (int nn=0;nn<8;nn++) acc[nn] = make_float4(0,0,0,0);

  #pragma unroll
  for (int p=0;p<2;p++){
    int srcBase = g*512 + p*256;
    if (p) __syncthreads();
    for (int i=tid; i<8192; i+=1024) S4[i] = Z4[srcBase*32 + i];
    __syncthreads();
    #pragma unroll
    for (int nn=0; nn<8; nn++){
      int ni = w*8 + nn;
      int n  = dstBase + ni;
      int jb = (p ? sp[ni]   : rb[ni])  - e0;
      int je = (p ? rb[ni+1] : sp[ni])  - e0;
      float4 a = acc[nn];
      if (p == half){
        float dv = g_dinv[n]; float swv = dv*dv;
        float4 z = S4[(n - srcBase)*32 + l];
        a.x = fmaf(swv,z.x,a.x); a.y = fmaf(swv,z.y,a.y);
        a.z = fmaf(swv,z.z,a.z); a.w = fmaf(swv,z.w,a.w);
      }
      int jeS = je < scnt ? je : scnt;
      int j = jb;
      for (; j+4 <= jeS; j += 4){
        int2 e0v = csrS[j], e1v = csrS[j+1], e2v = csrS[j+2], e3v = csrS[j+3];
        int i0 = (e0v.x-srcBase)*32+l, i1 = (e1v.x-srcBase)*32+l;
        int i2 = (e2v.x-srcBase)*32+l, i3 = (e3v.x-srcBase)*32+l;
        if (SAFE){ i0 &= 8191; i1 &= 8191; i2 &= 8191; i3 &= 8191; }
        float4 z0 = S4[i0], z1 = S4[i1], z2 = S4[i2], z3 = S4[i3];
        float w0 = __int_as_float(e0v.y), w1 = __int_as_float(e1v.y);
        float w2 = __int_as_float(e2v.y), w3 = __int_as_float(e3v.y);
        a.x = fmaf(w0,z0.x,a.x); a.y = fmaf(w0,z0.y,a.y); a.z = fmaf(w0,z0.z,a.z); a.w = fmaf(w0,z0.w,a.w);
        a.x = fmaf(w1,z1.x,a.x); a.y = fmaf(w1,z1.y,a.y); a.z = fmaf(w1,z1.z,a.z); a.w = fmaf(w1,z1.w,a.w);
        a.x = fmaf(w2,z2.x,a.x); a.y = fmaf(w2,z2.y,a.y); a.z = fmaf(w2,z2.z,a.z); a.w = fmaf(w2,z2.w,a.w);
        a.x = fmaf(w3,z3.x,a.x); a.y = fmaf(w3,z3.y,a.y); a.z = fmaf(w3,z3.z,a.z); a.w = fmaf(w3,z3.w,a.w);
      }
      for (; j < jeS; j++){
        int2 e = csrS[j];
        int gi = (e.x-srcBase)*32+l;
        if (SAFE) gi &= 8191;
        float4 zz = S4[gi];
        float ww = __int_as_float(e.y);
        a.x = fmaf(ww,zz.x,a.x); a.y = fmaf(ww,zz.y,a.y);
        a.z = fmaf(ww,zz.z,a.z); a.w = fmaf(ww,zz.w,a.w);
      }
      for (int jt = (jb > scnt ? jb : scnt); jt < je; jt++){
        int2 e = g_csr[e0 + jt];
        int gi = (e.x-srcBase)*32+l;
        if (SAFE) gi &= 8191;
        float4 zz = S4[gi];
        float ww = __int_as_float(e.y);
        a.x = fmaf(ww,zz.x,a.x); a.y = fmaf(ww,zz.y,a.y);
        a.z = fmaf(ww,zz.z,a.z); a.w = fmaf(ww,zz.w,a.w);
      }
      acc[nn] = a;
    }
  }
  float4 b4 = *(const float4*)&bias[l*4];
  float4 ssum = make_float4(0,0,0,0), ssq = make_float4(0,0,0,0);
  #pragma unroll
  for (int nn=0;nn<8;nn++){
    int n = dstBase + w*8 + nn;
    float4 a = acc[nn];
    a.x += b4.x; a.y += b4.y; a.z += b4.z; a.w += b4.w;
    R4[n*32 + l] = a;
    ssum.x += a.x; ssum.y += a.y; ssum.z += a.z; ssum.w += a.w;
    ssq.x = fmaf(a.x,a.x,ssq.x); ssq.y = fmaf(a.y,a.y,ssq.y);
    ssq.z = fmaf(a.z,a.z,ssq.z); ssq.w = fmaf(a.w,a.w,ssq.w);
  }
  __syncthreads();
  float* ssm = (float*)smraw;
  float* qsm = ssm + 32*128;
  ssm[w*128 + l*4+0] = ssum.x; ssm[w*128 + l*4+1] = ssum.y;
  ssm[w*128 + l*4+2] = ssum.z; ssm[w*128 + l*4+3] = ssum.w;
  qsm[w*128 + l*4+0] = ssq.x;  qsm[w*128 + l*4+1] = ssq.y;
  qsm[w*128 + l*4+2] = ssq.z;  qsm[w*128 + l*4+3] = ssq.w;
  __syncthreads();
  if (tid < 128){
    float s = 0.f;
    #pragma unroll
    for (int q=0;q<32;q++) s += ssm[q*128 + tid];
    statAdd(&g_isum[tid], s);
  } else if (tid < 256){
    int d = tid - 128;
    float s = 0.f;
    #pragma unroll
    for (int q=0;q<32;q++) s += qsm[q*128 + d];
    statAdd(&g_isq[d], s);
  }
  __threadfence();
  __syncthreads();
  if (tid == 0) isLast = (atomicAdd(&g_done, 1) == gridDim.x - 1);
  __syncthreads();
  if (isLast){
    if (tid < 128){
      unsigned long long us = atomicAdd(&g_isum[tid], 0ull);
      unsigned long long uq = atomicAdd(&g_isq[tid],  0ull);
      double s = (double)(long long)us;
      double q = (double)(long long)uq;
      double mean = s / ((double)QS * NN);
      double var  = q / ((double)QS * NN) - mean*mean;
      float sc = gm[tid] * rsqrtf((float)var + EPSC);
      g_scale[tid] = sc;
      g_shift[tid] = bt[tid] - (float)mean*sc;
      g_isum[tid] = 0ull; g_isq[tid] = 0ull;
    }
    if (tid == 0) g_done = 0;
  }
}

// ---------------- pooling ----------------
__global__ __launch_bounds__(256) void k_finmean(float* __restrict__ out,
                                                 const float* __restrict__ Watt){
  __shared__ float4 red4[8][32];
  __shared__ float mca[128];
  int b = blockIdx.x, tid = threadIdx.x;
  int c4 = tid & 31, g0 = tid >> 5;
  float4 sc = *(const float4*)&g_scale[c4*4];
  float4 sh = *(const float4*)&g_shift[c4*4];
  const float4* R4 = (const float4*)g_raw;
  float4* Z4 = (float4*)g_Z;
  float4* O4 = (float4*)out;
  float4 acc = make_float4(0,0,0,0);
  for (int i=0;i<64;i++){
    int n = b*512 + g0 + 8*i;
    float4 v = R4[n*32 + c4];
    float4 h;
    h.x = fmaxf(fmaf(v.x, sc.x, sh.x), 0.f);
    h.y = fmaxf(fmaf(v.y, sc.y, sh.y), 0.f);
    h.z = fmaxf(fmaf(v.z, sc.z, sh.z), 0.f);
    h.w = fmaxf(fmaf(v.w, sc.w, sh.w), 0.f);
    Z4[n*32 + c4] = h;
    O4[(size_t)n*64 + c4] = h;
    acc.x += h.x; acc.y += h.y; acc.z += h.z; acc.w += h.w;
  }
  red4[g0][c4] = acc;
  __syncthreads();
  if (tid < 32){
    float4 t = make_float4(0,0,0,0);
    #pragma unroll
    for (int q=0;q<8;q++){ float4 r = red4[q][tid]; t.x+=r.x; t.y+=r.y; t.z+=r.z; t.w+=r.w; }
    float inv = 1.f/512.f;
    mca[tid*4+0] = t.x*inv; mca[tid*4+1] = t.y*inv;
    mca[tid*4+2] = t.z*inv; mca[tid*4+3] = t.w*inv;
  }
  __syncthreads();
  if (tid < 128){
    float s = 0.f;
    #pragma unroll 8
    for (int k=0;k<128;k++) s = fmaf(mca[k], Watt[k*128 + tid], s);
    g_tgB[b*128 + tid] = tanhf(s);
  }
}

__global__ __launch_bounds__(256) void k_pool(float* __restrict__ out){
  __shared__ float4 tgs[32];
  __shared__ float4 red4[8][32];
  __shared__ float4 gfs[32];
  int b = blockIdx.x, tid = threadIdx.x, w = tid>>5, l = tid&31;
  if (tid < 32) tgs[tid] = ((const float4*)g_tgB)[b*32 + tid];
  __syncthreads();
  const float4* Z4 = (const float4*)g_Z;
  float4 gacc = make_float4(0,0,0,0);
  for (int i=0;i<64;i++){
    int n = b*512 + w + 8*i;
    float4 h = Z4[n*32 + l];
    float4 t = tgs[l];
    float d = h.x*t.x + h.y*t.y + h.z*t.z + h.w*t.w;
    #pragma unroll
    for (int off=16; off; off>>=1) d += __shfl_xor_sync(0xffffffffu, d, off);
    float coef = 1.f/(1.f + expf(-10.f*d));
    gacc.x = fmaf(coef, h.x, gacc.x); gacc.y = fmaf(coef, h.y, gacc.y);
    gacc.z = fmaf(coef, h.z, gacc.z); gacc.w = fmaf(coef, h.w, gacc.w);
  }
  red4[w][l] = gacc;
  __syncthreads();
  if (tid < 32){
    float4 t = make_float4(0,0,0,0);
    #pragma unroll
    for (int q=0;q<8;q++){ float4 r = red4[q][tid]; t.x+=r.x; t.y+=r.y; t.z+=r.z; t.w+=r.w; }
    gfs[tid] = t;
  }
  __syncthreads();
  float4* O4 = (float4*)out;
  float4 gf = gfs[l];
  for (int i=0;i<64;i++){
    int n = b*512 + w + 8*i;
    O4[(size_t)n*64 + 32 + l] = gf;
  }
}

// ---------------- launch ----------------
extern "C" void kernel_launch(void* const* d_in, const int* in_sizes, int n_in,
                              void* d_out, int out_size){
  const float* x    = (const float*)d_in[0];
  const int*   esrc = (const int*)  d_in[1];
  const int*   edst = (const int*)  d_in[2];
  const float* W0   = (const float*)d_in[4];
  const float* b0   = (const float*)d_in[5];
  const float* Wr   = (const float*)d_in[6];
  const float* br   = (const float*)d_in[7];
  const float* gm   = (const float*)d_in[8];
  const float* bt   = (const float*)d_in[9];
  const float* Watt = (const float*)d_in[10];
  float* out = (float*)d_out;

  cudaFuncSetAttribute(k_gemm,   cudaFuncAttributeMaxDynamicSharedMemorySize, GEMM_SMEM);
  cudaFuncSetAttribute(k_agg<0>, cudaFuncAttributeMaxDynamicSharedMemorySize, AGG_SMEM);
  cudaFuncSetAttribute(k_agg<1>, cudaFuncAttributeMaxDynamicSharedMemorySize, AGG_SMEM);

  k_count<<<EE/256, 256>>>(edst);
  k_scan <<<1, 1024>>>();
  k_fill <<<EE/256, 256>>>(esrc, edst);

  // launch #4 = SAFE agg probe for ncu's capture slot. csr is valid but
  // unsorted; split computed in-kernel stays within row bounds; SAFE masks
  // gather indices. All outputs (g_raw, stats, scale/shift, g_done) are
  // overwritten or self-reset before any live consumer.
  k_agg<1><<<2*BB, 1024, AGG_SMEM>>>(br, gm, bt);

  k_sraw0<<<NN/8, 256>>>(x, W0, b0, gm, bt);

  for (int l = 0; l < 9; l++){
    k_gemm  <<<296, 256, GEMM_SMEM>>>(Wr + (size_t)l*DD*DD);
    k_agg<0><<<2*BB, 1024, AGG_SMEM>>>(br + (size_t)l*DD,
                                       gm + (size_t)(l+1)*DD,
                                       bt + (size_t)(l+1)*DD);
  }

  k_finmean<<<BB, 256>>>(out, Watt);
  k_pool   <<<BB, 256>>>(out);
}

// round 15
// speedup vs baseline: 1.0355x; 1.0355x over previous
#include <cuda_runtime.h>
#include <math.h>

#define NN   32768
#define DD   128
#define EE   524288
#define BB   64
#define EPSC 1e-5f
#define QS   1048576.0f   // 2^20 fixed-point scale for deterministic BN stats
#define CAPE 4608         // per-CTA csr smem capacity (avg 4096, +8 sigma)

// ---------------- static device scratch (no allocation allowed) ----------------
__device__ float g_raw[NN*DD];
__device__ float g_Z[NN*DD];
__device__ float g_dinv[NN];
__device__ int   g_indeg[NN];      // statically zero; k_scan re-zeroes after read
__device__ int   g_rowoff[NN+1];
__device__ int   g_cursor[NN];
__device__ int2  g_csr[EE];        // after k_sraw0: (.x = local_src*32, .y = weight)
__device__ unsigned long long g_isum[DD];
__device__ unsigned long long g_isq[DD];
__device__ int   g_done;
__device__ float g_scale[DD];
__device__ float g_shift[DD];
__device__ float g_tgB[BB*DD];

// ---------------- f32x2 helpers (packed fp32, exact numerics) ----------------
typedef unsigned long long u64t;
__device__ __forceinline__ u64t pk2(float lo, float hi){
  u64t r; asm("mov.b64 %0,{%1,%2};" : "=l"(r) : "f"(lo), "f"(hi)); return r;
}
__device__ __forceinline__ void upk2(u64t v, float &lo, float &hi){
  asm("mov.b64 {%0,%1},%2;" : "=f"(lo), "=f"(hi) : "l"(v));
}
__device__ __forceinline__ void fma2(u64t &d, u64t a, u64t b){
  asm("fma.rn.f32x2 %0,%1,%2,%0;" : "+l"(d) : "l"(a), "l"(b));
}

__device__ __forceinline__ void statAdd(unsigned long long* p, float v){
  long long q = __float2ll_rn(v * QS);
  atomicAdd(p, (unsigned long long)q);
}

// ---------------- graph preprocessing ----------------
__global__ void k_count(const int* __restrict__ edst){
  int e = blockIdx.x*256 + threadIdx.x;
  if (e < EE) atomicAdd(&g_indeg[edst[e]], 1);
}

__global__ void k_scan(){
  __shared__ int sm[1024];
  int t = threadIdx.x;
  int base = t*32;
  int v[32]; int tot = 0;
  #pragma unroll
  for (int i=0;i<32;i++){ v[i] = g_indeg[base+i]; tot += v[i]; g_indeg[base+i] = 0; }
  sm[t] = tot;
  __syncthreads();
  for (int off=1; off<1024; off<<=1){
    int x = (t>=off) ? sm[t-off] : 0;
    __syncthreads();
    sm[t] += x;
    __syncthreads();
  }
  int run = sm[t] - tot;
  #pragma unroll
  for (int i=0;i<32;i++){
    g_rowoff[base+i] = run;
    g_cursor[base+i] = run;
    g_dinv[base+i]   = rsqrtf(1.0f + (float)v[i]);
    run += v[i];
  }
  if (t == 1023) g_rowoff[NN] = run;
}

__global__ void k_fill(const int* __restrict__ esrc, const int* __restrict__ edst){
  int e = blockIdx.x*256 + threadIdx.x;
  if (e >= EE) return;
  int s = esrc[e], d = edst[e];
  float w = g_dinv[s]*g_dinv[d];
  int p = atomicAdd(&g_cursor[d], 1);
  g_csr[p] = make_int2(s, __float_as_int(w));
}

// -------- sraw0 v3: warp-per-node rank sort (writes back PRESCALED src) ------
// After this kernel, g_csr[.].x = (src - graphbase)*32  (sorted ascending).
__global__ __launch_bounds__(256) void k_sraw0(const float* __restrict__ x,
    const float* __restrict__ W0, const float* __restrict__ b0,
    const float* __restrict__ gm, const float* __restrict__ bt){
  __shared__ int2 rowA[8][64];
  __shared__ int2 rowB[8][64];
  __shared__ float sS[8], sQ[8];
  __shared__ bool isLast;
  int tid = threadIdx.x, w = tid>>5, l = tid&31;
  int n = blockIdx.x*8 + w;
  int gb = n & ~511;
  int r0 = g_rowoff[n], r1 = g_rowoff[n+1];
  int len = r1 - r0;
  float s;
  if (len <= 64){
    if (l < len)      rowA[w][l]      = g_csr[r0 + l];
    if (32 + l < len) rowA[w][32 + l] = g_csr[r0 + 32 + l];
    __syncwarp();
    for (int p = l; p < len; p += 32){
      int2 key = rowA[w][p];
      int rank = 0;
      for (int i = 0; i < len; i++){
        int2 o = rowA[w][i];
        rank += (o.x < key.x) || (o.x == key.x && i < p);
      }
      rowB[w][rank] = key;
      g_csr[r0 + rank] = make_int2((key.x - gb)*32, key.y);  // prescaled writeback
    }
    __syncwarp();
    float part = 0.f;
    if (l < len){      int2 e = rowB[w][l];      part = __int_as_float(e.y) * x[e.x]; }
    if (32 + l < len){ int2 e = rowB[w][32 + l]; part = fmaf(__int_as_float(e.y), x[e.x], part); }
    #pragma unroll
    for (int off=16; off; off>>=1) part += __shfl_xor_sync(0xffffffffu, part, off);
    float dv = g_dinv[n];
    s = fmaf(dv*dv, x[n], part);
  } else {
    if (l == 0){
      for (int i = r0+1; i < r1; i++){
        int2 key = g_csr[i];
        int j = i-1;
        while (j >= r0 && g_csr[j].x > key.x){ g_csr[j+1] = g_csr[j]; j--; }
        g_csr[j+1] = key;
      }
    }
    __syncwarp();
    float part = 0.f;
    for (int j = r0 + l; j < r1; j += 32){
      int2 e = g_csr[j];
      part = fmaf(__int_as_float(e.y), x[e.x], part);
    }
    #pragma unroll
    for (int off=16; off; off>>=1) part += __shfl_xor_sync(0xffffffffu, part, off);
    __syncwarp();
    for (int j = r0 + l; j < r1; j += 32){    // prescale after use
      int2 e = g_csr[j];
      g_csr[j] = make_int2((e.x - gb)*32, e.y);
    }
    float dv = g_dinv[n];
    s = fmaf(dv*dv, x[n], part);
  }
  {
    float4 W4 = *(const float4*)&W0[l*4];
    float4 b4 = *(const float4*)&b0[l*4];
    float4 r;
    r.x = fmaf(s, W4.x, b4.x);
    r.y = fmaf(s, W4.y, b4.y);
    r.z = fmaf(s, W4.z, b4.z);
    r.w = fmaf(s, W4.w, b4.w);
    ((float4*)g_raw)[n*32 + l] = r;
  }
  if (l == 0){ sS[w] = s; sQ[w] = s*s; }
  __syncthreads();
  if (tid == 0){
    float S = 0.f, Q = 0.f;
    #pragma unroll
    for (int q=0;q<8;q++){ S += sS[q]; Q += sQ[q]; }
    statAdd(&g_isum[0], S);
    statAdd(&g_isq[0],  Q);
  }
  __threadfence();
  __syncthreads();
  if (tid == 0) isLast = (atomicAdd(&g_done, 1) == gridDim.x - 1);
  __syncthreads();
  if (isLast){
    if (tid < 128){
      unsigned long long us = atomicAdd(&g_isum[0], 0ull);
      unsigned long long uq = atomicAdd(&g_isq[0],  0ull);
      double S = (double)(long long)us / (double)QS;
      double Q = (double)(long long)uq / (double)QS;
      double mS = S / NN;
      double vS = Q / NN - mS*mS;
      double wv = (double)W0[tid];
      float mean = (float)(wv*mS + (double)b0[tid]);
      float var  = (float)(wv*wv*vS);
      float sc = gm[tid] * rsqrtf(var + EPSC);
      g_scale[tid] = sc;
      g_shift[tid] = bt[tid] - mean*sc;
      g_isum[tid] = 0ull; g_isq[tid] = 0ull;
    }
    if (tid == 0) g_done = 0;
  }
}

// ---------------- GEMM v4 (best known): k-split f32x2 packing -----------------
#define GEMM_SMEM (64*132*4 + 64*128*8)
__global__ __launch_bounds__(256,2) void k_gemm(const float* __restrict__ W){
  extern __shared__ float smem[];
  float (*As)[132] = (float(*)[132])smem;          // [64][132]
  u64t* WT = (u64t*)(smem + 64*132);               // [64][128]
  int tid = threadIdx.x;
  int w = tid>>5, l = tid&31;
  int w8 = w*8;
  #pragma unroll
  for (int i=0;i<8;i++){
    int f = tid + i*256;            // 0..2047
    int kp = f>>5, c4 = f&31;
    float4 wa = ((const float4*)W)[(2*kp)*32 + c4];
    float4 wb = ((const float4*)W)[(2*kp+1)*32 + c4];
    ulonglong2 p0, p1;
    p0.x = pk2(wa.x, wb.x); p0.y = pk2(wa.y, wb.y);
    p1.x = pk2(wa.z, wb.z); p1.y = pk2(wa.w, wb.w);
    *(ulonglong2*)&WT[kp*128 + c4*4]     = p0;
    *(ulonglong2*)&WT[kp*128 + c4*4 + 2] = p1;
  }
  const float4* A4g = (const float4*)g_raw;
  for (int t = blockIdx.x; t < NN/64; t += 296){
    int row0 = t*64;
    __syncthreads();
    #pragma unroll
    for (int i=0;i<8;i++){
      int f = tid + i*256;
      int r = f>>5, k4 = f&31;
      float4 v  = A4g[(row0+r)*32 + k4];
      float4 sc = *(const float4*)&g_scale[k4*4];
      float4 sh = *(const float4*)&g_shift[k4*4];
      float4 h;
      h.x = fmaxf(fmaf(v.x, sc.x, sh.x), 0.f);
      h.y = fmaxf(fmaf(v.y, sc.y, sh.y), 0.f);
      h.z = fmaxf(fmaf(v.z, sc.z, sh.z), 0.f);
      h.w = fmaxf(fmaf(v.w, sc.w, sh.w), 0.f);
      *(float4*)&As[r][k4*4] = h;
    }
    __syncthreads();
    u64t acc[8][4];
    #pragma unroll
    for (int r=0;r<8;r++)
      #pragma unroll
      for (int c=0;c<4;c++) acc[r][c] = 0ull;
    #pragma unroll 4
    for (int kq=0;kq<32;kq++){
      u64t w0 = WT[(2*kq)*128 + l];
      u64t w1 = WT[(2*kq)*128 + 32 + l];
      u64t w2 = WT[(2*kq)*128 + 64 + l];
      u64t w3 = WT[(2*kq)*128 + 96 + l];
      u64t v0 = WT[(2*kq+1)*128 + l];
      u64t v1 = WT[(2*kq+1)*128 + 32 + l];
      u64t v2 = WT[(2*kq+1)*128 + 64 + l];
      u64t v3 = WT[(2*kq+1)*128 + 96 + l];
      #pragma unroll
      for (int r=0;r<8;r++){
        ulonglong2 ar = *(const ulonglong2*)&As[w8+r][kq*4];
        fma2(acc[r][0], ar.x, w0); fma2(acc[r][1], ar.x, w1);
        fma2(acc[r][2], ar.x, w2); fma2(acc[r][3], ar.x, w3);
        fma2(acc[r][0], ar.y, v0); fma2(acc[r][1], ar.y, v1);
        fma2(acc[r][2], ar.y, v2); fma2(acc[r][3], ar.y, v3);
      }
    }
    #pragma unroll
    for (int r=0;r<8;r++){
      int row = row0 + w8 + r;
      float lo, hi;
      upk2(acc[r][0], lo, hi); g_Z[row*128 + l]      = lo + hi;
      upk2(acc[r][1], lo, hi); g_Z[row*128 + 32 + l] = lo + hi;
      upk2(acc[r][2], lo, hi); g_Z[row*128 + 64 + l] = lo + hi;
      upk2(acc[r][3], lo, hi); g_Z[row*128 + 96 + l] = lo + hi;
    }
  }
}

// ------- aggregation v7: prescaled csr + software-pipelined batches -----------
#define AGG_SMEM (131072 + CAPE*8 + (258+256)*4)
__global__ __launch_bounds__(1024) void k_agg(const float* __restrict__ bias,
                                              const float* __restrict__ gm,
                                              const float* __restrict__ bt){
  extern __shared__ char smraw[];
  float4* S4  = (float4*)smraw;
  int2*  csrS = (int2*)(smraw + 131072);
  int*   rb   = (int*)(smraw + 131072 + CAPE*8);
  int*   sp   = rb + 258;
  __shared__ bool isLast;
  int c = blockIdx.x, g = c>>1, half = c&1;
  int dstBase = g*512 + half*256;
  int tid = threadIdx.x, w = tid>>5, l = tid&31;
  const float4* Z4 = (const float4*)g_Z;
  float4* R4 = (float4*)g_raw;
  if (tid < 257) rb[tid] = g_rowoff[dstBase + tid];
  int e0 = g_rowoff[dstBase];
  int ecnt = g_rowoff[dstBase + 256] - e0;
  int scnt = ecnt < CAPE ? ecnt : CAPE;
  for (int i = tid; i < scnt; i += 1024) csrS[i] = g_csr[e0 + i];
  __syncthreads();
  if (tid < 256){
    int lo = rb[tid] - e0, hi = rb[tid+1] - e0;
    while (lo < hi){                        // first entry with local*32 >= 8192
      int mid = (lo + hi) >> 1;
      int2 e = (mid < scnt) ? csrS[mid] : g_csr[e0 + mid];
      if (e.x >= 8192) hi = mid; else lo = mid + 1;
    }
    sp[tid] = lo + e0;
  }
  __syncthreads();

  float4 acc[8];
  #pragma unroll
  for (int nn=0;nn<8;nn++) acc[nn] = make_float4(0,0,0,0);

  #pragma unroll
  for (int p=0;p<2;p++){
    int srcBase = g*512 + p*256;
    int off = l - p*8192;                    // gather idx = e.x + off
    if (p) __syncthreads();
    for (int i=tid; i<8192; i+=1024) S4[i] = Z4[srcBase*32 + i];
    __syncthreads();
    #pragma unroll
    for (int nn=0; nn<8; nn++){
      int ni = w*8 + nn;
      int n  = dstBase + ni;
      int jb = (p ? sp[ni]   : rb[ni])  - e0;
      int je = (p ? rb[ni+1] : sp[ni])  - e0;
      float4 a = acc[nn];
      if (p == half){
        float dv = g_dinv[n]; float swv = dv*dv;
        float4 z = S4[(n - srcBase)*32 + l];
        a.x = fmaf(swv,z.x,a.x); a.y = fmaf(swv,z.y,a.y);
        a.z = fmaf(swv,z.z,a.z); a.w = fmaf(swv,z.w,a.w);
      }
      int jeS = je < scnt ? je : scnt;
      int j = jb;
      if (j + 4 <= jeS){
        int2 c0 = csrS[j], c1 = csrS[j+1], c2 = csrS[j+2], c3 = csrS[j+3];
        while (true){
          int2 e0v=c0, e1v=c1, e2v=c2, e3v=c3;
          int jn = j + 4;
          bool more = (jn + 4 <= jeS);
          if (more){ c0=csrS[jn]; c1=csrS[jn+1]; c2=csrS[jn+2]; c3=csrS[jn+3]; }
          float4 z0 = S4[e0v.x + off], z1 = S4[e1v.x + off];
          float4 z2 = S4[e2v.x + off], z3 = S4[e3v.x + off];
          float w0 = __int_as_float(e0v.y), w1 = __int_as_float(e1v.y);
          float w2 = __int_as_float(e2v.y), w3 = __int_as_float(e3v.y);
          a.x = fmaf(w0,z0.x,a.x); a.y = fmaf(w0,z0.y,a.y); a.z = fmaf(w0,z0.z,a.z); a.w = fmaf(w0,z0.w,a.w);
          a.x = fmaf(w1,z1.x,a.x); a.y = fmaf(w1,z1.y,a.y); a.z = fmaf(w1,z1.z,a.z); a.w = fmaf(w1,z1.w,a.w);
          a.x = fmaf(w2,z2.x,a.x); a.y = fmaf(w2,z2.y,a.y); a.z = fmaf(w2,z2.z,a.z); a.w = fmaf(w2,z2.w,a.w);
          a.x = fmaf(w3,z3.x,a.x); a.y = fmaf(w3,z3.y,a.y); a.z = fmaf(w3,z3.z,a.z); a.w = fmaf(w3,z3.w,a.w);
          j = jn;
          if (!more) break;
        }
      }
      for (; j < jeS; j++){
        int2 e = csrS[j];
        float4 zz = S4[e.x + off];
        float ww = __int_as_float(e.y);
        a.x = fmaf(ww,zz.x,a.x); a.y = fmaf(ww,zz.y,a.y);
        a.z = fmaf(ww,zz.z,a.z); a.w = fmaf(ww,zz.w,a.w);
      }
      for (int jt = (jb > scnt ? jb : scnt); jt < je; jt++){
        int2 e = g_csr[e0 + jt];
        float4 zz = S4[e.x + off];
        float ww = __int_as_float(e.y);
        a.x = fmaf(ww,zz.x,a.x); a.y = fmaf(ww,zz.y,a.y);
        a.z = fmaf(ww,zz.z,a.z); a.w = fmaf(ww,zz.w,a.w);
      }
      acc[nn] = a;
    }
  }
  float4 b4 = *(const float4*)&bias[l*4];
  float4 ssum = make_float4(0,0,0,0), ssq = make_float4(0,0,0,0);
  #pragma unroll
  for (int nn=0;nn<8;nn++){
    int n = dstBase + w*8 + nn;
    float4 a = acc[nn];
    a.x += b4.x; a.y += b4.y; a.z += b4.z; a.w += b4.w;
    R4[n*32 + l] = a;
    ssum.x += a.x; ssum.y += a.y; ssum.z += a.z; ssum.w += a.w;
    ssq.x = fmaf(a.x,a.x,ssq.x); ssq.y = fmaf(a.y,a.y,ssq.y);
    ssq.z = fmaf(a.z,a.z,ssq.z); ssq.w = fmaf(a.w,a.w,ssq.w);
  }
  __syncthreads();
  float* ssm = (float*)smraw;
  float* qsm = ssm + 32*128;
  ssm[w*128 + l*4+0] = ssum.x; ssm[w*128 + l*4+1] = ssum.y;
  ssm[w*128 + l*4+2] = ssum.z; ssm[w*128 + l*4+3] = ssum.w;
  qsm[w*128 + l*4+0] = ssq.x;  qsm[w*128 + l*4+1] = ssq.y;
  qsm[w*128 + l*4+2] = ssq.z;  qsm[w*128 + l*4+3] = ssq.w;
  __syncthreads();
  if (tid < 128){
    float s = 0.f;
    #pragma unroll
    for (int q=0;q<32;q++) s += ssm[q*128 + tid];
    statAdd(&g_isum[tid], s);
  } else if (tid < 256){
    int d = tid - 128;
    float s = 0.f;
    #pragma unroll
    for (int q=0;q<32;q++) s += qsm[q*128 + d];
    statAdd(&g_isq[d], s);
  }
  __threadfence();
  __syncthreads();
  if (tid == 0) isLast = (atomicAdd(&g_done, 1) == gridDim.x - 1);
  __syncthreads();
  if (isLast){
    if (tid < 128){
      unsigned long long us = atomicAdd(&g_isum[tid], 0ull);
      unsigned long long uq = atomicAdd(&g_isq[tid],  0ull);
      double s = (double)(long long)us;
      double q = (double)(long long)uq;
      double mean = s / ((double)QS * NN);
      double var  = q / ((double)QS * NN) - mean*mean;
      float sc = gm[tid] * rsqrtf((float)var + EPSC);
      g_scale[tid] = sc;
      g_shift[tid] = bt[tid] - (float)mean*sc;
      g_isum[tid] = 0ull; g_isq[tid] = 0ull;
    }
    if (tid == 0) g_done = 0;
  }
}

// ---------------- pooling ----------------
__global__ __launch_bounds__(256) void k_finmean(float* __restrict__ out,
                                                 const float* __restrict__ Watt){
  __shared__ float4 red4[8][32];
  __shared__ float mca[128];
  int b = blockIdx.x, tid = threadIdx.x;
  int c4 = tid & 31, g0 = tid >> 5;
  float4 sc = *(const float4*)&g_scale[c4*4];
  float4 sh = *(const float4*)&g_shift[c4*4];
  const float4* R4 = (const float4*)g_raw;
  float4* Z4 = (float4*)g_Z;
  float4* O4 = (float4*)out;
  float4 acc = make_float4(0,0,0,0);
  for (int i=0;i<64;i++){
    int n = b*512 + g0 + 8*i;
    float4 v = R4[n*32 + c4];
    float4 h;
    h.x = fmaxf(fmaf(v.x, sc.x, sh.x), 0.f);
    h.y = fmaxf(fmaf(v.y, sc.y, sh.y), 0.f);
    h.z = fmaxf(fmaf(v.z, sc.z, sh.z), 0.f);
    h.w = fmaxf(fmaf(v.w, sc.w, sh.w), 0.f);
    Z4[n*32 + c4] = h;
    O4[(size_t)n*64 + c4] = h;
    acc.x += h.x; acc.y += h.y; acc.z += h.z; acc.w += h.w;
  }
  red4[g0][c4] = acc;
  __syncthreads();
  if (tid < 32){
    float4 t = make_float4(0,0,0,0);
    #pragma unroll
    for (int q=0;q<8;q++){ float4 r = red4[q][tid]; t.x+=r.x; t.y+=r.y; t.z+=r.z; t.w+=r.w; }
    float inv = 1.f/512.f;
    mca[tid*4+0] = t.x*inv; mca[tid*4+1] = t.y*inv;
    mca[tid*4+2] = t.z*inv; mca[tid*4+3] = t.w*inv;
  }
  __syncthreads();
  if (tid < 128){
    float s = 0.f;
    #pragma unroll 8
    for (int k=0;k<128;k++) s = fmaf(mca[k], Watt[k*128 + tid], s);
    g_tgB[b*128 + tid] = tanhf(s);
  }
}

__global__ __launch_bounds__(256) void k_pool(float* __restrict__ out){
  __shared__ float4 tgs[32];
  __shared__ float4 red4[8][32];
  __shared__ float4 gfs[32];
  int b = blockIdx.x, tid = threadIdx.x, w = tid>>5, l = tid&31;
  if (tid < 32) tgs[tid] = ((const float4*)g_tgB)[b*32 + tid];
  __syncthreads();
  const float4* Z4 = (const float4*)g_Z;
  float4 gacc = make_float4(0,0,0,0);
  for (int i=0;i<64;i++){
    int n = b*512 + w + 8*i;
    float4 h = Z4[n*32 + l];
    float4 t = tgs[l];
    float d = h.x*t.x + h.y*t.y + h.z*t.z + h.w*t.w;
    #pragma unroll
    for (int off=16; off; off>>=1) d += __shfl_xor_sync(0xffffffffu, d, off);
    float coef = 1.f/(1.f + expf(-10.f*d));
    gacc.x = fmaf(coef, h.x, gacc.x); gacc.y = fmaf(coef, h.y, gacc.y);
    gacc.z = fmaf(coef, h.z, gacc.z); gacc.w = fmaf(coef, h.w, gacc.w);
  }
  red4[w][l] = gacc;
  __syncthreads();
  if (tid < 32){
    float4 t = make_float4(0,0,0,0);
    #pragma unroll
    for (int q=0;q<8;q++){ float4 r = red4[q][tid]; t.x+=r.x; t.y+=r.y; t.z+=r.z; t.w+=r.w; }
    gfs[tid] = t;
  }
  __syncthreads();
  float4* O4 = (float4*)out;
  float4 gf = gfs[l];
  for (int i=0;i<64;i++){
    int n = b*512 + w + 8*i;
    O4[(size_t)n*64 + 32 + l] = gf;
  }
}

// ---------------- launch ----------------
extern "C" void kernel_launch(void* const* d_in, const int* in_sizes, int n_in,
                              void* d_out, int out_size){
  const float* x    = (const float*)d_in[0];
  const int*   esrc = (const int*)  d_in[1];
  const int*   edst = (const int*)  d_in[2];
  const float* W0   = (const float*)d_in[4];
  const float* b0   = (const float*)d_in[5];
  const float* Wr   = (const float*)d_in[6];
  const float* br   = (const float*)d_in[7];
  const float* gm   = (const float*)d_in[8];
  const float* bt   = (const float*)d_in[9];
  const float* Watt = (const float*)d_in[10];
  float* out = (float*)d_out;

  cudaFuncSetAttribute(k_gemm, cudaFuncAttributeMaxDynamicSharedMemorySize, GEMM_SMEM);
  cudaFuncSetAttribute(k_agg,  cudaFuncAttributeMaxDynamicSharedMemorySize, AGG_SMEM);

  k_count<<<EE/256, 256>>>(edst);
  k_scan <<<1, 1024>>>();
  k_fill <<<EE/256, 256>>>(esrc, edst);
  k_sraw0<<<NN/8, 256>>>(x, W0, b0, gm, bt);

  for (int l = 0; l < 9; l++){
    k_gemm<<<296, 256, GEMM_SMEM>>>(Wr + (size_t)l*DD*DD);
    k_agg <<<2*BB, 1024, AGG_SMEM>>>(br + (size_t)l*DD,
                                     gm + (size_t)(l+1)*DD,
                                     bt + (size_t)(l+1)*DD);
  }

  k_finmean<<<BB, 256>>>(out, Watt);
  k_pool   <<<BB, 256>>>(out);
}

// round 16
// speedup vs baseline: 1.0410x; 1.0053x over previous
#include <cuda_runtime.h>
#include <math.h>

#define NN   32768
#define DD   128
#define EE   524288
#define BB   64
#define EPSC 1e-5f
#define QS   1048576.0f   // 2^20 fixed-point scale for deterministic BN stats
#define CAPE 4608         // per-CTA csr smem capacity (avg 4096, +8 sigma)

// ---------------- static device scratch (no allocation allowed) ----------------
__device__ float g_raw[NN*DD];
__device__ float g_Z[NN*DD];
__device__ float g_dinv[NN];
__device__ int   g_indeg[NN];      // statically zero; k_scan re-zeroes after read
__device__ int   g_rowoff[NN+1];
__device__ int   g_cursor[NN];
__device__ int2  g_csr[EE];        // after k_sraw0: (.x = local_src*32, .y = weight)
__device__ unsigned long long g_isum[DD];
__device__ unsigned long long g_isq[DD];
__device__ int   g_done;
__device__ float g_scale[DD];
__device__ float g_shift[DD];
__device__ float g_tgB[BB*DD];

// ---------------- f32x2 helpers (packed fp32, exact numerics) ----------------
typedef unsigned long long u64t;
__device__ __forceinline__ u64t pk2(float lo, float hi){
  u64t r; asm("mov.b64 %0,{%1,%2};" : "=l"(r) : "f"(lo), "f"(hi)); return r;
}
__device__ __forceinline__ void upk2(u64t v, float &lo, float &hi){
  asm("mov.b64 {%0,%1},%2;" : "=f"(lo), "=f"(hi) : "l"(v));
}
__device__ __forceinline__ void fma2(u64t &d, u64t a, u64t b){
  asm("fma.rn.f32x2 %0,%1,%2,%0;" : "+l"(d) : "l"(a), "l"(b));
}

__device__ __forceinline__ void statAdd(unsigned long long* p, float v){
  long long q = __float2ll_rn(v * QS);
  atomicAdd(p, (unsigned long long)q);
}

// ---------------- graph preprocessing v2: per-graph smem atomics ----------------
__global__ __launch_bounds__(256) void k_count(const int* __restrict__ edst){
  __shared__ int hist[512];
  int g = blockIdx.x, tid = threadIdx.x;
  for (int i = tid; i < 512; i += 256) hist[i] = 0;
  __syncthreads();
  const int* ed = edst + g*8192;
  for (int i = tid; i < 8192; i += 256) atomicAdd(&hist[ed[i] & 511], 1);
  __syncthreads();
  for (int i = tid; i < 512; i += 256) g_indeg[g*512 + i] = hist[i];
}

__global__ void k_scan(){
  __shared__ int sm[1024];
  int t = threadIdx.x;
  int base = t*32;
  int v[32]; int tot = 0;
  #pragma unroll
  for (int i=0;i<32;i++){ v[i] = g_indeg[base+i]; tot += v[i]; g_indeg[base+i] = 0; }
  sm[t] = tot;
  __syncthreads();
  for (int off=1; off<1024; off<<=1){
    int x = (t>=off) ? sm[t-off] : 0;
    __syncthreads();
    sm[t] += x;
    __syncthreads();
  }
  int run = sm[t] - tot;
  #pragma unroll
  for (int i=0;i<32;i++){
    g_rowoff[base+i] = run;
    g_dinv[base+i]   = rsqrtf(1.0f + (float)v[i]);
    run += v[i];
  }
  if (t == 1023) g_rowoff[NN] = run;
}

__global__ __launch_bounds__(256) void k_fill(const int* __restrict__ esrc,
                                              const int* __restrict__ edst){
  __shared__ int cur[512];
  int g = blockIdx.x, tid = threadIdx.x;
  int gb = g*512;
  for (int i = tid; i < 512; i += 256) cur[i] = g_rowoff[gb + i];
  __syncthreads();
  const int* es = esrc + g*8192;
  const int* ed = edst + g*8192;
  for (int i = tid; i < 8192; i += 256){
    int s = es[i], d = ed[i];
    float wv = g_dinv[s] * g_dinv[d];
    int p = atomicAdd(&cur[d & 511], 1);
    g_csr[p] = make_int2(s, __float_as_int(wv));
  }
}

// -------- sraw0 v3: warp-per-node rank sort (writes back PRESCALED src) ------
// After this kernel, g_csr[.].x = (src - graphbase)*32  (sorted ascending).
__global__ __launch_bounds__(256) void k_sraw0(const float* __restrict__ x,
    const float* __restrict__ W0, const float* __restrict__ b0,
    const float* __restrict__ gm, const float* __restrict__ bt){
  __shared__ int2 rowA[8][64];
  __shared__ int2 rowB[8][64];
  __shared__ float sS[8], sQ[8];
  __shared__ bool isLast;
  int tid = threadIdx.x, w = tid>>5, l = tid&31;
  int n = blockIdx.x*8 + w;
  int gb = n & ~511;
  int r0 = g_rowoff[n], r1 = g_rowoff[n+1];
  int len = r1 - r0;
  float s;
  if (len <= 64){
    if (l < len)      rowA[w][l]      = g_csr[r0 + l];
    if (32 + l < len) rowA[w][32 + l] = g_csr[r0 + 32 + l];
    __syncwarp();
    for (int p = l; p < len; p += 32){
      int2 key = rowA[w][p];
      int rank = 0;
      for (int i = 0; i < len; i++){
        int2 o = rowA[w][i];
        rank += (o.x < key.x) || (o.x == key.x && i < p);
      }
      rowB[w][rank] = key;
      g_csr[r0 + rank] = make_int2((key.x - gb)*32, key.y);  // prescaled writeback
    }
    __syncwarp();
    float part = 0.f;
    if (l < len){      int2 e = rowB[w][l];      part = __int_as_float(e.y) * x[e.x]; }
    if (32 + l < len){ int2 e = rowB[w][32 + l]; part = fmaf(__int_as_float(e.y), x[e.x], part); }
    #pragma unroll
    for (int off=16; off; off>>=1) part += __shfl_xor_sync(0xffffffffu, part, off);
    float dv = g_dinv[n];
    s = fmaf(dv*dv, x[n], part);
  } else {
    if (l == 0){
      for (int i = r0+1; i < r1; i++){
        int2 key = g_csr[i];
        int j = i-1;
        while (j >= r0 && g_csr[j].x > key.x){ g_csr[j+1] = g_csr[j]; j--; }
        g_csr[j+1] = key;
      }
    }
    __syncwarp();
    float part = 0.f;
    for (int j = r0 + l; j < r1; j += 32){
      int2 e = g_csr[j];
      part = fmaf(__int_as_float(e.y), x[e.x], part);
    }
    #pragma unroll
    for (int off=16; off; off>>=1) part += __shfl_xor_sync(0xffffffffu, part, off);
    __syncwarp();
    for (int j = r0 + l; j < r1; j += 32){
      int2 e = g_csr[j];
      g_csr[j] = make_int2((e.x - gb)*32, e.y);
    }
    float dv = g_dinv[n];
    s = fmaf(dv*dv, x[n], part);
  }
  {
    float4 W4 = *(const float4*)&W0[l*4];
    float4 b4 = *(const float4*)&b0[l*4];
    float4 r;
    r.x = fmaf(s, W4.x, b4.x);
    r.y = fmaf(s, W4.y, b4.y);
    r.z = fmaf(s, W4.z, b4.z);
    r.w = fmaf(s, W4.w, b4.w);
    ((float4*)g_raw)[n*32 + l] = r;
  }
  if (l == 0){ sS[w] = s; sQ[w] = s*s; }
  __syncthreads();
  if (tid == 0){
    float S = 0.f, Q = 0.f;
    #pragma unroll
    for (int q=0;q<8;q++){ S += sS[q]; Q += sQ[q]; }
    statAdd(&g_isum[0], S);
    statAdd(&g_isq[0],  Q);
  }
  __threadfence();
  __syncthreads();
  if (tid == 0) isLast = (atomicAdd(&g_done, 1) == gridDim.x - 1);
  __syncthreads();
  if (isLast){
    if (tid < 128){
      unsigned long long us = atomicAdd(&g_isum[0], 0ull);
      unsigned long long uq = atomicAdd(&g_isq[0],  0ull);
      double S = (double)(long long)us / (double)QS;
      double Q = (double)(long long)uq / (double)QS;
      double mS = S / NN;
      double vS = Q / NN - mS*mS;
      double wv = (double)W0[tid];
      float mean = (float)(wv*mS + (double)b0[tid]);
      float var  = (float)(wv*wv*vS);
      float sc = gm[tid] * rsqrtf(var + EPSC);
      g_scale[tid] = sc;
      g_shift[tid] = bt[tid] - mean*sc;
      g_isum[tid] = 0ull; g_isq[tid] = 0ull;
    }
    if (tid == 0) g_done = 0;
  }
}

// ------- GEMM v7: 512 thr, within-CTA column split (warp = 8 rows x 64 cols) ---
// A tile staged ONCE (no duplication); 32 warps/SM for 2x latency hiding;
// crossbar/k = 128 cyc = fma demand (balanced).
#define GEMM_SMEM (64*132*4 + 64*128*8)
__global__ __launch_bounds__(512,2) void k_gemm(const float* __restrict__ W){
  extern __shared__ float smem[];
  float (*As)[132] = (float(*)[132])smem;          // [64][132]
  u64t* WT = (u64t*)(smem + 64*132);               // [64][128]
  int tid = threadIdx.x;
  int w = tid>>5, l = tid&31;
  int rg = (w>>1)*8;            // row-group base (8 rows)
  int c0 = (w&1)*64;            // column half
  #pragma unroll
  for (int i=0;i<4;i++){
    int f = tid + i*512;        // 0..2047
    int kp = f>>5, c4 = f&31;
    float4 wa = ((const float4*)W)[(2*kp)*32 + c4];
    float4 wb = ((const float4*)W)[(2*kp+1)*32 + c4];
    ulonglong2 p0, p1;
    p0.x = pk2(wa.x, wb.x); p0.y = pk2(wa.y, wb.y);
    p1.x = pk2(wa.z, wb.z); p1.y = pk2(wa.w, wb.w);
    *(ulonglong2*)&WT[kp*128 + c4*4]     = p0;
    *(ulonglong2*)&WT[kp*128 + c4*4 + 2] = p1;
  }
  const float4* A4g = (const float4*)g_raw;
  for (int t = blockIdx.x; t < NN/64; t += 296){
    int row0 = t*64;
    __syncthreads();
    #pragma unroll
    for (int i=0;i<4;i++){
      int f = tid + i*512;
      int r = f>>5, k4 = f&31;
      float4 v  = A4g[(row0+r)*32 + k4];
      float4 sc = *(const float4*)&g_scale[k4*4];
      float4 sh = *(const float4*)&g_shift[k4*4];
      float4 h;
      h.x = fmaxf(fmaf(v.x, sc.x, sh.x), 0.f);
      h.y = fmaxf(fmaf(v.y, sc.y, sh.y), 0.f);
      h.z = fmaxf(fmaf(v.z, sc.z, sh.z), 0.f);
      h.w = fmaxf(fmaf(v.w, sc.w, sh.w), 0.f);
      *(float4*)&As[r][k4*4] = h;
    }
    __syncthreads();
    u64t acc[8][2];
    #pragma unroll
    for (int r=0;r<8;r++){ acc[r][0] = 0ull; acc[r][1] = 0ull; }
    #pragma unroll 4
    for (int kq=0;kq<32;kq++){
      u64t w0 = WT[(2*kq)*128 + c0 + l];
      u64t w1 = WT[(2*kq)*128 + c0 + 32 + l];
      u64t v0 = WT[(2*kq+1)*128 + c0 + l];
      u64t v1 = WT[(2*kq+1)*128 + c0 + 32 + l];
      #pragma unroll
      for (int r=0;r<8;r++){
        ulonglong2 ar = *(const ulonglong2*)&As[rg+r][kq*4];
        fma2(acc[r][0], ar.x, w0); fma2(acc[r][1], ar.x, w1);
        fma2(acc[r][0], ar.y, v0); fma2(acc[r][1], ar.y, v1);
      }
    }
    #pragma unroll
    for (int r=0;r<8;r++){
      int row = row0 + rg + r;
      float lo, hi;
      upk2(acc[r][0], lo, hi); g_Z[row*128 + c0 + l]      = lo + hi;
      upk2(acc[r][1], lo, hi); g_Z[row*128 + c0 + 32 + l] = lo + hi;
    }
  }
}

// ------- aggregation v7 (R15): prescaled csr + software-pipelined batches -----
#define AGG_SMEM (131072 + CAPE*8 + (258+256)*4)
__global__ __launch_bounds__(1024) void k_agg(const float* __restrict__ bias,
                                              const float* __restrict__ gm,
                                              const float* __restrict__ bt){
  extern __shared__ char smraw[];
  float4* S4  = (float4*)smraw;
  int2*  csrS = (int2*)(smraw + 131072);
  int*   rb   = (int*)(smraw + 131072 + CAPE*8);
  int*   sp   = rb + 258;
  __shared__ bool isLast;
  int c = blockIdx.x, g = c>>1, half = c&1;
  int dstBase = g*512 + half*256;
  int tid = threadIdx.x, w = tid>>5, l = tid&31;
  const float4* Z4 = (const float4*)g_Z;
  float4* R4 = (float4*)g_raw;
  if (tid < 257) rb[tid] = g_rowoff[dstBase + tid];
  int e0 = g_rowoff[dstBase];
  int ecnt = g_rowoff[dstBase + 256] - e0;
  int scnt = ecnt < CAPE ? ecnt : CAPE;
  for (int i = tid; i < scnt; i += 1024) csrS[i] = g_csr[e0 + i];
  __syncthreads();
  if (tid < 256){
    int lo = rb[tid] - e0, hi = rb[tid+1] - e0;
    while (lo < hi){                        // first entry with local*32 >= 8192
      int mid = (lo + hi) >> 1;
      int2 e = (mid < scnt) ? csrS[mid] : g_csr[e0 + mid];
      if (e.x >= 8192) hi = mid; else lo = mid + 1;
    }
    sp[tid] = lo + e0;
  }
  __syncthreads();

  float4 acc[8];
  #pragma unroll
  for (int nn=0;nn<8;nn++) acc[nn] = make_float4(0,0,0,0);

  #pragma unroll
  for (int p=0;p<2;p++){
    int srcBase = g*512 + p*256;
    int off = l - p*8192;                    // gather idx = e.x + off
    if (p) __syncthreads();
    for (int i=tid; i<8192; i+=1024) S4[i] = Z4[srcBase*32 + i];
    __syncthreads();
    #pragma unroll
    for (int nn=0; nn<8; nn++){
      int ni = w*8 + nn;
      int n  = dstBase + ni;
      int jb = (p ? sp[ni]   : rb[ni])  - e0;
      int je = (p ? rb[ni+1] : sp[ni])  - e0;
      float4 a = acc[nn];
      if (p == half){
        float dv = g_dinv[n]; float swv = dv*dv;
        float4 z = S4[(n - srcBase)*32 + l];
        a.x = fmaf(swv,z.x,a.x); a.y = fmaf(swv,z.y,a.y);
        a.z = fmaf(swv,z.z,a.z); a.w = fmaf(swv,z.w,a.w);
      }
      int jeS = je < scnt ? je : scnt;
      int j = jb;
      if (j + 4 <= jeS){
        int2 c0v = csrS[j], c1v = csrS[j+1], c2v = csrS[j+2], c3v = csrS[j+3];
        while (true){
          int2 e0v=c0v, e1v=c1v, e2v=c2v, e3v=c3v;
          int jn = j + 4;
          bool more = (jn + 4 <= jeS);
          if (more){ c0v=csrS[jn]; c1v=csrS[jn+1]; c2v=csrS[jn+2]; c3v=csrS[jn+3]; }
          float4 z0 = S4[e0v.x + off], z1 = S4[e1v.x + off];
          float4 z2 = S4[e2v.x + off], z3 = S4[e3v.x + off];
          float w0 = __int_as_float(e0v.y), w1 = __int_as_float(e1v.y);
          float w2 = __int_as_float(e2v.y), w3 = __int_as_float(e3v.y);
          a.x = fmaf(w0,z0.x,a.x); a.y = fmaf(w0,z0.y,a.y); a.z = fmaf(w0,z0.z,a.z); a.w = fmaf(w0,z0.w,a.w);
          a.x = fmaf(w1,z1.x,a.x); a.y = fmaf(w1,z1.y,a.y); a.z = fmaf(w1,z1.z,a.z); a.w = fmaf(w1,z1.w,a.w);
          a.x = fmaf(w2,z2.x,a.x); a.y = fmaf(w2,z2.y,a.y); a.z = fmaf(w2,z2.z,a.z); a.w = fmaf(w2,z2.w,a.w);
          a.x = fmaf(w3,z3.x,a.x); a.y = fmaf(w3,z3.y,a.y); a.z = fmaf(w3,z3.z,a.z); a.w = fmaf(w3,z3.w,a.w);
          j = jn;
          if (!more) break;
        }
      }
      for (; j < jeS; j++){
        int2 e = csrS[j];
        float4 zz = S4[e.x + off];
        float ww = __int_as_float(e.y);
        a.x = fmaf(ww,zz.x,a.x); a.y = fmaf(ww,zz.y,a.y);
        a.z = fmaf(ww,zz.z,a.z); a.w = fmaf(ww,zz.w,a.w);
      }
      for (int jt = (jb > scnt ? jb : scnt); jt < je; jt++){
        int2 e = g_csr[e0 + jt];
        float4 zz = S4[e.x + off];
        float ww = __int_as_float(e.y);
        a.x = fmaf(ww,zz.x,a.x); a.y = fmaf(ww,zz.y,a.y);
        a.z = fmaf(ww,zz.z,a.z); a.w = fmaf(ww,zz.w,a.w);
      }
      acc[nn] = a;
    }
  }
  float4 b4 = *(const float4*)&bias[l*4];
  float4 ssum = make_float4(0,0,0,0), ssq = make_float4(0,0,0,0);
  #pragma unroll
  for (int nn=0;nn<8;nn++){
    int n = dstBase + w*8 + nn;
    float4 a = acc[nn];
    a.x += b4.x; a.y += b4.y; a.z += b4.z; a.w += b4.w;
    R4[n*32 + l] = a;
    ssum.x += a.x; ssum.y += a.y; ssum.z += a.z; ssum.w += a.w;
    ssq.x = fmaf(a.x,a.x,ssq.x); ssq.y = fmaf(a.y,a.y,ssq.y);
    ssq.z = fmaf(a.z,a.z,ssq.z); ssq.w = fmaf(a.w,a.w,ssq.w);
  }
  __syncthreads();
  float* ssm = (float*)smraw;
  float* qsm = ssm + 32*128;
  ssm[w*128 + l*4+0] = ssum.x; ssm[w*128 + l*4+1] = ssum.y;
  ssm[w*128 + l*4+2] = ssum.z; ssm[w*128 + l*4+3] = ssum.w;
  qsm[w*128 + l*4+0] = ssq.x;  qsm[w*128 + l*4+1] = ssq.y;
  qsm[w*128 + l*4+2] = ssq.z;  qsm[w*128 + l*4+3] = ssq.w;
  __syncthreads();
  if (tid < 128){
    float s = 0.f;
    #pragma unroll
    for (int q=0;q<32;q++) s += ssm[q*128 + tid];
    statAdd(&g_isum[tid], s);
  } else if (tid < 256){
    int d = tid - 128;
    float s = 0.f;
    #pragma unroll
    for (int q=0;q<32;q++) s += qsm[q*128 + d];
    statAdd(&g_isq[d], s);
  }
  __threadfence();
  __syncthreads();
  if (tid == 0) isLast = (atomicAdd(&g_done, 1) == gridDim.x - 1);
  __syncthreads();
  if (isLast){
    if (tid < 128){
      unsigned long long us = atomicAdd(&g_isum[tid], 0ull);
      unsigned long long uq = atomicAdd(&g_isq[tid],  0ull);
      double s = (double)(long long)us;
      double q = (double)(long long)uq;
      double mean = s / ((double)QS * NN);
      double var  = q / ((double)QS * NN) - mean*mean;
      float sc = gm[tid] * rsqrtf((float)var + EPSC);
      g_scale[tid] = sc;
      g_shift[tid] = bt[tid] - (float)mean*sc;
      g_isum[tid] = 0ull; g_isq[tid] = 0ull;
    }
    if (tid == 0) g_done = 0;
  }
}

// ---------------- pooling ----------------
__global__ __launch_bounds__(256) void k_finmean(float* __restrict__ out,
                                                 const float* __restrict__ Watt){
  __shared__ float4 red4[8][32];
  __shared__ float mca[128];
  int b = blockIdx.x, tid = threadIdx.x;
  int c4 = tid & 31, g0 = tid >> 5;
  float4 sc = *(const float4*)&g_scale[c4*4];
  float4 sh = *(const float4*)&g_shift[c4*4];
  const float4* R4 = (const float4*)g_raw;
  float4* Z4 = (float4*)g_Z;
  float4* O4 = (float4*)out;
  float4 acc = make_float4(0,0,0,0);
  for (int i=0;i<64;i++){
    int n = b*512 + g0 + 8*i;
    float4 v = R4[n*32 + c4];
    float4 h;
    h.x = fmaxf(fmaf(v.x, sc.x, sh.x), 0.f);
    h.y = fmaxf(fmaf(v.y, sc.y, sh.y), 0.f);
    h.z = fmaxf(fmaf(v.z, sc.z, sh.z), 0.f);
    h.w = fmaxf(fmaf(v.w, sc.w, sh.w), 0.f);
    Z4[n*32 + c4] = h;
    O4[(size_t)n*64 + c4] = h;
    acc.x += h.x; acc.y += h.y; acc.z += h.z; acc.w += h.w;
  }
  red4[g0][c4] = acc;
  __syncthreads();
  if (tid < 32){
    float4 t = make_float4(0,0,0,0);
    #pragma unroll
    for (int q=0;q<8;q++){ float4 r = red4[q][tid]; t.x+=r.x; t.y+=r.y; t.z+=r.z; t.w+=r.w; }
    float inv = 1.f/512.f;
    mca[tid*4+0] = t.x*inv; mca[tid*4+1] = t.y*inv;
    mca[tid*4+2] = t.z*inv; mca[tid*4+3] = t.w*inv;
  }
  __syncthreads();
  if (tid < 128){
    float s = 0.f;
    #pragma unroll 8
    for (int k=0;k<128;k++) s = fmaf(mca[k], Watt[k*128 + tid], s);
    g_tgB[b*128 + tid] = tanhf(s);
  }
}

__global__ __launch_bounds__(256) void k_pool(float* __restrict__ out){
  __shared__ float4 tgs[32];
  __shared__ float4 red4[8][32];
  __shared__ float4 gfs[32];
  int b = blockIdx.x, tid = threadIdx.x, w = tid>>5, l = tid&31;
  if (tid < 32) tgs[tid] = ((const float4*)g_tgB)[b*32 + tid];
  __syncthreads();
  const float4* Z4 = (const float4*)g_Z;
  float4 gacc = make_float4(0,0,0,0);
  for (int i=0;i<64;i++){
    int n = b*512 + w + 8*i;
    float4 h = Z4[n*32 + l];
    float4 t = tgs[l];
    float d = h.x*t.x + h.y*t.y + h.z*t.z + h.w*t.w;
    #pragma unroll
    for (int off=16; off; off>>=1) d += __shfl_xor_sync(0xffffffffu, d, off);
    float coef = 1.f/(1.f + expf(-10.f*d));
    gacc.x = fmaf(coef, h.x, gacc.x); gacc.y = fmaf(coef, h.y, gacc.y);
    gacc.z = fmaf(coef, h.z, gacc.z); gacc.w = fmaf(coef, h.w, gacc.w);
  }
  red4[w][l] = gacc;
  __syncthreads();
  if (tid < 32){
    float4 t = make_float4(0,0,0,0);
    #pragma unroll
    for (int q=0;q<8;q++){ float4 r = red4[q][tid]; t.x+=r.x; t.y+=r.y; t.z+=r.z; t.w+=r.w; }
    gfs[tid] = t;
  }
  __syncthreads();
  float4* O4 = (float4*)out;
  float4 gf = gfs[l];
  for (int i=0;i<64;i++){
    int n = b*512 + w + 8*i;
    O4[(size_t)n*64 + 32 + l] = gf;
  }
}

// ---------------- launch ----------------
extern "C" void kernel_launch(void* const* d_in, const int* in_sizes, int n_in,
                              void* d_out, int out_size){
  const float* x    = (const float*)d_in[0];
  const int*   esrc = (const int*)  d_in[1];
  const int*   edst = (const int*)  d_in[2];
  const float* W0   = (const float*)d_in[4];
  const float* b0   = (const float*)d_in[5];
  const float* Wr   = (const float*)d_in[6];
  const float* br   = (const float*)d_in[7];
  const float* gm   = (const float*)d_in[8];
  const float* bt   = (const float*)d_in[9];
  const float* Watt = (const float*)d_in[10];
  float* out = (float*)d_out;

  cudaFuncSetAttribute(k_gemm, cudaFuncAttributeMaxDynamicSharedMemorySize, GEMM_SMEM);
  cudaFuncSetAttribute(k_agg,  cudaFuncAttributeMaxDynamicSharedMemorySize, AGG_SMEM);

  k_count<<<BB, 256>>>(edst);
  k_scan <<<1, 1024>>>();
  k_fill <<<BB, 256>>>(esrc, edst);
  k_sraw0<<<NN/8, 256>>>(x, W0, b0, gm, bt);

  for (int l = 0; l < 9; l++){
    k_gemm<<<296, 512, GEMM_SMEM>>>(Wr + (size_t)l*DD*DD);
    k_agg <<<2*BB, 1024, AGG_SMEM>>>(br + (size_t)l*DD,
                                     gm + (size_t)(l+1)*DD,
                                     bt + (size_t)(l+1)*DD);
  }

  k_finmean<<<BB, 256>>>(out, Watt);
  k_pool   <<<BB, 256>>>(out);
}

// round 17
// speedup vs baseline: 1.1031x; 1.0596x over previous
#include <cuda_runtime.h>
#include <math.h>

#define NN   32768
#define DD   128
#define EE   524288
#define BB   64
#define EPSC 1e-5f
#define QS   1048576.0f   // 2^20 fixed-point scale for deterministic BN stats
#define CAPE 4608         // per-CTA csr smem capacity (avg 4096, +8 sigma)

// ---------------- static device scratch (no allocation allowed) ----------------
__device__ float g_raw[NN*DD];
__device__ float g_Z[NN*DD];
__device__ float g_dinv[NN];
__device__ int   g_indeg[NN];
__device__ int   g_rowoff[NN+1];
__device__ int2  g_csr[EE];        // after k_sraw0: (.x = local_src*32, .y = weight)
__device__ unsigned long long g_isum[DD];
__device__ unsigned long long g_isq[DD];
__device__ int   g_done;
__device__ float g_scale[DD];
__device__ float g_shift[DD];

// ---------------- f32x2 helpers (packed fp32, exact numerics) ----------------
typedef unsigned long long u64t;
__device__ __forceinline__ u64t pk2(float lo, float hi){
  u64t r; asm("mov.b64 %0,{%1,%2};" : "=l"(r) : "f"(lo), "f"(hi)); return r;
}
__device__ __forceinline__ void upk2(u64t v, float &lo, float &hi){
  asm("mov.b64 {%0,%1},%2;" : "=f"(lo), "=f"(hi) : "l"(v));
}
__device__ __forceinline__ void fma2(u64t &d, u64t a, u64t b){
  asm("fma.rn.f32x2 %0,%1,%2,%0;" : "+l"(d) : "l"(a), "l"(b));
}

__device__ __forceinline__ void statAdd(unsigned long long* p, float v){
  long long q = __float2ll_rn(v * QS);
  atomicAdd(p, (unsigned long long)q);
}

// ---------------- graph preprocessing v2: per-graph smem atomics ----------------
__global__ __launch_bounds__(256) void k_count(const int* __restrict__ edst){
  __shared__ int hist[512];
  int g = blockIdx.x, tid = threadIdx.x;
  for (int i = tid; i < 512; i += 256) hist[i] = 0;
  __syncthreads();
  const int* ed = edst + g*8192;
  for (int i = tid; i < 8192; i += 256) atomicAdd(&hist[ed[i] & 511], 1);
  __syncthreads();
  for (int i = tid; i < 512; i += 256) g_indeg[g*512 + i] = hist[i];
}

__global__ void k_scan(){
  __shared__ int sm[1024];
  int t = threadIdx.x;
  int base = t*32;
  int v[32]; int tot = 0;
  #pragma unroll
  for (int i=0;i<32;i++){ v[i] = g_indeg[base+i]; tot += v[i]; }
  sm[t] = tot;
  __syncthreads();
  for (int off=1; off<1024; off<<=1){
    int x = (t>=off) ? sm[t-off] : 0;
    __syncthreads();
    sm[t] += x;
    __syncthreads();
  }
  int run = sm[t] - tot;
  #pragma unroll
  for (int i=0;i<32;i++){
    g_rowoff[base+i] = run;
    g_dinv[base+i]   = rsqrtf(1.0f + (float)v[i]);
    run += v[i];
  }
  if (t == 1023) g_rowoff[NN] = run;
}

__global__ __launch_bounds__(256) void k_fill(const int* __restrict__ esrc,
                                              const int* __restrict__ edst){
  __shared__ int cur[512];
  int g = blockIdx.x, tid = threadIdx.x;
  int gb = g*512;
  for (int i = tid; i < 512; i += 256) cur[i] = g_rowoff[gb + i];
  __syncthreads();
  const int* es = esrc + g*8192;
  const int* ed = edst + g*8192;
  for (int i = tid; i < 8192; i += 256){
    int s = es[i], d = ed[i];
    float wv = g_dinv[s] * g_dinv[d];
    int p = atomicAdd(&cur[d & 511], 1);
    g_csr[p] = make_int2(s, __float_as_int(wv));
  }
}

// -------- sraw0 v3: warp-per-node rank sort (writes back PRESCALED src) ------
__global__ __launch_bounds__(256) void k_sraw0(const float* __restrict__ x,
    const float* __restrict__ W0, const float* __restrict__ b0,
    const float* __restrict__ gm, const float* __restrict__ bt){
  __shared__ int2 rowA[8][64];
  __shared__ int2 rowB[8][64];
  __shared__ float sS[8], sQ[8];
  __shared__ bool isLast;
  int tid = threadIdx.x, w = tid>>5, l = tid&31;
  int n = blockIdx.x*8 + w;
  int gb = n & ~511;
  int r0 = g_rowoff[n], r1 = g_rowoff[n+1];
  int len = r1 - r0;
  float s;
  if (len <= 64){
    if (l < len)      rowA[w][l]      = g_csr[r0 + l];
    if (32 + l < len) rowA[w][32 + l] = g_csr[r0 + 32 + l];
    __syncwarp();
    for (int p = l; p < len; p += 32){
      int2 key = rowA[w][p];
      int rank = 0;
      for (int i = 0; i < len; i++){
        int2 o = rowA[w][i];
        rank += (o.x < key.x) || (o.x == key.x && i < p);
      }
      rowB[w][rank] = key;
      g_csr[r0 + rank] = make_int2((key.x - gb)*32, key.y);
    }
    __syncwarp();
    float part = 0.f;
    if (l < len){      int2 e = rowB[w][l];      part = __int_as_float(e.y) * x[e.x]; }
    if (32 + l < len){ int2 e = rowB[w][32 + l]; part = fmaf(__int_as_float(e.y), x[e.x], part); }
    #pragma unroll
    for (int off=16; off; off>>=1) part += __shfl_xor_sync(0xffffffffu, part, off);
    float dv = g_dinv[n];
    s = fmaf(dv*dv, x[n], part);
  } else {
    if (l == 0){
      for (int i = r0+1; i < r1; i++){
        int2 key = g_csr[i];
        int j = i-1;
        while (j >= r0 && g_csr[j].x > key.x){ g_csr[j+1] = g_csr[j]; j--; }
        g_csr[j+1] = key;
      }
    }
    __syncwarp();
    float part = 0.f;
    for (int j = r0 + l; j < r1; j += 32){
      int2 e = g_csr[j];
      part = fmaf(__int_as_float(e.y), x[e.x], part);
    }
    #pragma unroll
    for (int off=16; off; off>>=1) part += __shfl_xor_sync(0xffffffffu, part, off);
    __syncwarp();
    for (int j = r0 + l; j < r1; j += 32){
      int2 e = g_csr[j];
      g_csr[j] = make_int2((e.x - gb)*32, e.y);
    }
    float dv = g_dinv[n];
    s = fmaf(dv*dv, x[n], part);
  }
  {
    float4 W4 = *(const float4*)&W0[l*4];
    float4 b4 = *(const float4*)&b0[l*4];
    float4 r;
    r.x = fmaf(s, W4.x, b4.x);
    r.y = fmaf(s, W4.y, b4.y);
    r.z = fmaf(s, W4.z, b4.z);
    r.w = fmaf(s, W4.w, b4.w);
    ((float4*)g_raw)[n*32 + l] = r;
  }
  if (l == 0){ sS[w] = s; sQ[w] = s*s; }
  __syncthreads();
  if (tid == 0){
    float S = 0.f, Q = 0.f;
    #pragma unroll
    for (int q=0;q<8;q++){ S += sS[q]; Q += sQ[q]; }
    statAdd(&g_isum[0], S);
    statAdd(&g_isq[0],  Q);
  }
  __threadfence();
  __syncthreads();
  if (tid == 0) isLast = (atomicAdd(&g_done, 1) == gridDim.x - 1);
  __syncthreads();
  if (isLast){
    if (tid < 128){
      unsigned long long us = atomicAdd(&g_isum[0], 0ull);
      unsigned long long uq = atomicAdd(&g_isq[0],  0ull);
      double S = (double)(long long)us / (double)QS;
      double Q = (double)(long long)uq / (double)QS;
      double mS = S / NN;
      double vS = Q / NN - mS*mS;
      double wv = (double)W0[tid];
      float mean = (float)(wv*mS + (double)b0[tid]);
      float var  = (float)(wv*wv*vS);
      float sc = gm[tid] * rsqrtf(var + EPSC);
      g_scale[tid] = sc;
      g_shift[tid] = bt[tid] - mean*sc;
      g_isum[tid] = 0ull; g_isq[tid] = 0ull;
    }
    if (tid == 0) g_done = 0;
  }
}

// ---------------- GEMM v4 (best known): k-split f32x2 packing -----------------
#define GEMM_SMEM (64*132*4 + 64*128*8)
__global__ __launch_bounds__(256,2) void k_gemm(const float* __restrict__ W){
  extern __shared__ float smem[];
  float (*As)[132] = (float(*)[132])smem;          // [64][132]
  u64t* WT = (u64t*)(smem + 64*132);               // [64][128]
  int tid = threadIdx.x;
  int w = tid>>5, l = tid&31;
  int w8 = w*8;
  #pragma unroll
  for (int i=0;i<8;i++){
    int f = tid + i*256;            // 0..2047
    int kp = f>>5, c4 = f&31;
    float4 wa = ((const float4*)W)[(2*kp)*32 + c4];
    float4 wb = ((const float4*)W)[(2*kp+1)*32 + c4];
    ulonglong2 p0, p1;
    p0.x = pk2(wa.x, wb.x); p0.y = pk2(wa.y, wb.y);
    p1.x = pk2(wa.z, wb.z); p1.y = pk2(wa.w, wb.w);
    *(ulonglong2*)&WT[kp*128 + c4*4]     = p0;
    *(ulonglong2*)&WT[kp*128 + c4*4 + 2] = p1;
  }
  const float4* A4g = (const float4*)g_raw;
  for (int t = blockIdx.x; t < NN/64; t += 296){
    int row0 = t*64;
    __syncthreads();
    #pragma unroll
    for (int i=0;i<8;i++){
      int f = tid + i*256;
      int r = f>>5, k4 = f&31;
      float4 v  = A4g[(row0+r)*32 + k4];
      float4 sc = *(const float4*)&g_scale[k4*4];
      float4 sh = *(const float4*)&g_shift[k4*4];
      float4 h;
      h.x = fmaxf(fmaf(v.x, sc.x, sh.x), 0.f);
      h.y = fmaxf(fmaf(v.y, sc.y, sh.y), 0.f);
      h.z = fmaxf(fmaf(v.z, sc.z, sh.z), 0.f);
      h.w = fmaxf(fmaf(v.w, sc.w, sh.w), 0.f);
      *(float4*)&As[r][k4*4] = h;
    }
    __syncthreads();
    u64t acc[8][4];
    #pragma unroll
    for (int r=0;r<8;r++)
      #pragma unroll
      for (int c=0;c<4;c++) acc[r][c] = 0ull;
    #pragma unroll 4
    for (int kq=0;kq<32;kq++){
      u64t w0 = WT[(2*kq)*128 + l];
      u64t w1 = WT[(2*kq)*128 + 32 + l];
      u64t w2 = WT[(2*kq)*128 + 64 + l];
      u64t w3 = WT[(2*kq)*128 + 96 + l];
      u64t v0 = WT[(2*kq+1)*128 + l];
      u64t v1 = WT[(2*kq+1)*128 + 32 + l];
      u64t v2 = WT[(2*kq+1)*128 + 64 + l];
      u64t v3 = WT[(2*kq+1)*128 + 96 + l];
      #pragma unroll
      for (int r=0;r<8;r++){
        ulonglong2 ar = *(const ulonglong2*)&As[w8+r][kq*4];
        fma2(acc[r][0], ar.x, w0); fma2(acc[r][1], ar.x, w1);
        fma2(acc[r][2], ar.x, w2); fma2(acc[r][3], ar.x, w3);
        fma2(acc[r][0], ar.y, v0); fma2(acc[r][1], ar.y, v1);
        fma2(acc[r][2], ar.y, v2); fma2(acc[r][3], ar.y, v3);
      }
    }
    #pragma unroll
    for (int r=0;r<8;r++){
      int row = row0 + w8 + r;
      float lo, hi;
      upk2(acc[r][0], lo, hi); g_Z[row*128 + l]      = lo + hi;
      upk2(acc[r][1], lo, hi); g_Z[row*128 + 32 + l] = lo + hi;
      upk2(acc[r][2], lo, hi); g_Z[row*128 + 64 + l] = lo + hi;
      upk2(acc[r][3], lo, hi); g_Z[row*128 + 96 + l] = lo + hi;
    }
  }
}

// ------- aggregation v7: prescaled csr + software-pipelined batches -----------
#define AGG_SMEM (131072 + CAPE*8 + (258+256)*4)
__global__ __launch_bounds__(1024) void k_agg(const float* __restrict__ bias,
                                              const float* __restrict__ gm,
                                              const float* __restrict__ bt){
  extern __shared__ char smraw[];
  float4* S4  = (float4*)smraw;
  int2*  csrS = (int2*)(smraw + 131072);
  int*   rb   = (int*)(smraw + 131072 + CAPE*8);
  int*   sp   = rb + 258;
  __shared__ bool isLast;
  int c = blockIdx.x, g = c>>1, half = c&1;
  int dstBase = g*512 + half*256;
  int tid = threadIdx.x, w = tid>>5, l = tid&31;
  const float4* Z4 = (const float4*)g_Z;
  float4* R4 = (float4*)g_raw;
  if (tid < 257) rb[tid] = g_rowoff[dstBase + tid];
  int e0 = g_rowoff[dstBase];
  int ecnt = g_rowoff[dstBase + 256] - e0;
  int scnt = ecnt < CAPE ? ecnt : CAPE;
  for (int i = tid; i < scnt; i += 1024) csrS[i] = g_csr[e0 + i];
  __syncthreads();
  if (tid < 256){
    int lo = rb[tid] - e0, hi = rb[tid+1] - e0;
    while (lo < hi){
      int mid = (lo + hi) >> 1;
      int2 e = (mid < scnt) ? csrS[mid] : g_csr[e0 + mid];
      if (e.x >= 8192) hi = mid; else lo = mid + 1;
    }
    sp[tid] = lo + e0;
  }
  __syncthreads();

  float4 acc[8];
  #pragma unroll
  for (int nn=0;nn<8;nn++) acc[nn] = make_float4(0,0,0,0);

  #pragma unroll
  for (int p=0;p<2;p++){
    int srcBase = g*512 + p*256;
    int off = l - p*8192;
    if (p) __syncthreads();
    for (int i=tid; i<8192; i+=1024) S4[i] = Z4[srcBase*32 + i];
    __syncthreads();
    #pragma unroll
    for (int nn=0; nn<8; nn++){
      int ni = w*8 + nn;
      int n  = dstBase + ni;
      int jb = (p ? sp[ni]   : rb[ni])  - e0;
      int je = (p ? rb[ni+1] : sp[ni])  - e0;
      float4 a = acc[nn];
      if (p == half){
        float dv = g_dinv[n]; float swv = dv*dv;
        float4 z = S4[(n - srcBase)*32 + l];
        a.x = fmaf(swv,z.x,a.x); a.y = fmaf(swv,z.y,a.y);
        a.z = fmaf(swv,z.z,a.z); a.w = fmaf(swv,z.w,a.w);
      }
      int jeS = je < scnt ? je : scnt;
      int j = jb;
      if (j + 4 <= jeS){
        int2 c0v = csrS[j], c1v = csrS[j+1], c2v = csrS[j+2], c3v = csrS[j+3];
        while (true){
          int2 e0v=c0v, e1v=c1v, e2v=c2v, e3v=c3v;
          int jn = j + 4;
          bool more = (jn + 4 <= jeS);
          if (more){ c0v=csrS[jn]; c1v=csrS[jn+1]; c2v=csrS[jn+2]; c3v=csrS[jn+3]; }
          float4 z0 = S4[e0v.x + off], z1 = S4[e1v.x + off];
          float4 z2 = S4[e2v.x + off], z3 = S4[e3v.x + off];
          float w0 = __int_as_float(e0v.y), w1 = __int_as_float(e1v.y);
          float w2 = __int_as_float(e2v.y), w3 = __int_as_float(e3v.y);
          a.x = fmaf(w0,z0.x,a.x); a.y = fmaf(w0,z0.y,a.y); a.z = fmaf(w0,z0.z,a.z); a.w = fmaf(w0,z0.w,a.w);
          a.x = fmaf(w1,z1.x,a.x); a.y = fmaf(w1,z1.y,a.y); a.z = fmaf(w1,z1.z,a.z); a.w = fmaf(w1,z1.w,a.w);
          a.x = fmaf(w2,z2.x,a.x); a.y = fmaf(w2,z2.y,a.y); a.z = fmaf(w2,z2.z,a.z); a.w = fmaf(w2,z2.w,a.w);
          a.x = fmaf(w3,z3.x,a.x); a.y = fmaf(w3,z3.y,a.y); a.z = fmaf(w3,z3.z,a.z); a.w = fmaf(w3,z3.w,a.w);
          j = jn;
          if (!more) break;
        }
      }
      for (; j < jeS; j++){
        int2 e = csrS[j];
        float4 zz = S4[e.x + off];
        float ww = __int_as_float(e.y);
        a.x = fmaf(ww,zz.x,a.x); a.y = fmaf(ww,zz.y,a.y);
        a.z = fmaf(ww,zz.z,a.z); a.w = fmaf(ww,zz.w,a.w);
      }
      for (int jt = (jb > scnt ? jb : scnt); jt < je; jt++){
        int2 e = g_csr[e0 + jt];
        float4 zz = S4[e.x + off];
        float ww = __int_as_float(e.y);
        a.x = fmaf(ww,zz.x,a.x); a.y = fmaf(ww,zz.y,a.y);
        a.z = fmaf(ww,zz.z,a.z); a.w = fmaf(ww,zz.w,a.w);
      }
      acc[nn] = a;
    }
  }
  float4 b4 = *(const float4*)&bias[l*4];
  float4 ssum = make_float4(0,0,0,0), ssq = make_float4(0,0,0,0);
  #pragma unroll
  for (int nn=0;nn<8;nn++){
    int n = dstBase + w*8 + nn;
    float4 a = acc[nn];
    a.x += b4.x; a.y += b4.y; a.z += b4.z; a.w += b4.w;
    R4[n*32 + l] = a;
    ssum.x += a.x; ssum.y += a.y; ssum.z += a.z; ssum.w += a.w;
    ssq.x = fmaf(a.x,a.x,ssq.x); ssq.y = fmaf(a.y,a.y,ssq.y);
    ssq.z = fmaf(a.z,a.z,ssq.z); ssq.w = fmaf(a.w,a.w,ssq.w);
  }
  __syncthreads();
  float* ssm = (float*)smraw;
  float* qsm = ssm + 32*128;
  ssm[w*128 + l*4+0] = ssum.x; ssm[w*128 + l*4+1] = ssum.y;
  ssm[w*128 + l*4+2] = ssum.z; ssm[w*128 + l*4+3] = ssum.w;
  qsm[w*128 + l*4+0] = ssq.x;  qsm[w*128 + l*4+1] = ssq.y;
  qsm[w*128 + l*4+2] = ssq.z;  qsm[w*128 + l*4+3] = ssq.w;
  __syncthreads();
  if (tid < 128){
    float s = 0.f;
    #pragma unroll
    for (int q=0;q<32;q++) s += ssm[q*128 + tid];
    statAdd(&g_isum[tid], s);
  } else if (tid < 256){
    int d = tid - 128;
    float s = 0.f;
    #pragma unroll
    for (int q=0;q<32;q++) s += qsm[q*128 + d];
    statAdd(&g_isq[d], s);
  }
  __threadfence();
  __syncthreads();
  if (tid == 0) isLast = (atomicAdd(&g_done, 1) == gridDim.x - 1);
  __syncthreads();
  if (isLast){
    if (tid < 128){
      unsigned long long us = atomicAdd(&g_isum[tid], 0ull);
      unsigned long long uq = atomicAdd(&g_isq[tid],  0ull);
      double s = (double)(long long)us;
      double q = (double)(long long)uq;
      double mean = s / ((double)QS * NN);
      double var  = q / ((double)QS * NN) - mean*mean;
      float sc = gm[tid] * rsqrtf((float)var + EPSC);
      g_scale[tid] = sc;
      g_shift[tid] = bt[tid] - (float)mean*sc;
      g_isum[tid] = 0ull; g_isq[tid] = 0ull;
    }
    if (tid == 0) g_done = 0;
  }
}

// ------- fused pooling: BN+ReLU + out[0:128] + mean + attention + out[128:256] -
__global__ __launch_bounds__(256) void k_poolall(float* __restrict__ out,
                                                 const float* __restrict__ Watt){
  __shared__ float4 red4[8][32];
  __shared__ float mca[128];
  __shared__ float4 tgs[32];
  __shared__ float4 gfs[32];
  int b = blockIdx.x, tid = threadIdx.x;
  int l = tid & 31, w = tid >> 5;
  float4 sc = *(const float4*)&g_scale[l*4];
  float4 sh = *(const float4*)&g_shift[l*4];
  const float4* R4 = (const float4*)g_raw;
  float4* Z4 = (float4*)g_Z;
  float4* O4 = (float4*)out;
  // phase 1: BN+ReLU, write Z + out lower half, accumulate mean
  float4 acc = make_float4(0,0,0,0);
  for (int i=0;i<64;i++){
    int n = b*512 + w + 8*i;
    float4 v = R4[n*32 + l];
    float4 h;
    h.x = fmaxf(fmaf(v.x, sc.x, sh.x), 0.f);
    h.y = fmaxf(fmaf(v.y, sc.y, sh.y), 0.f);
    h.z = fmaxf(fmaf(v.z, sc.z, sh.z), 0.f);
    h.w = fmaxf(fmaf(v.w, sc.w, sh.w), 0.f);
    Z4[n*32 + l] = h;
    O4[(size_t)n*64 + l] = h;
    acc.x += h.x; acc.y += h.y; acc.z += h.z; acc.w += h.w;
  }
  red4[w][l] = acc;
  __syncthreads();
  if (tid < 32){
    float4 t = make_float4(0,0,0,0);
    #pragma unroll
    for (int q=0;q<8;q++){ float4 r = red4[q][tid]; t.x+=r.x; t.y+=r.y; t.z+=r.z; t.w+=r.w; }
    float inv = 1.f/512.f;
    mca[tid*4+0] = t.x*inv; mca[tid*4+1] = t.y*inv;
    mca[tid*4+2] = t.z*inv; mca[tid*4+3] = t.w*inv;
  }
  __syncthreads();
  if (tid < 128){
    float s = 0.f;
    #pragma unroll 8
    for (int k=0;k<128;k++) s = fmaf(mca[k], Watt[k*128 + tid], s);
    ((float*)tgs)[tid] = tanhf(s);
  }
  __syncthreads();
  // phase 2: attention pooling over this graph's Z (same CTA wrote it)
  float4 tg = tgs[l];
  float4 gacc = make_float4(0,0,0,0);
  for (int i=0;i<64;i++){
    int n = b*512 + w + 8*i;
    float4 h = Z4[n*32 + l];
    float d = h.x*tg.x + h.y*tg.y + h.z*tg.z + h.w*tg.w;
    #pragma unroll
    for (int off=16; off; off>>=1) d += __shfl_xor_sync(0xffffffffu, d, off);
    float coef = 1.f/(1.f + expf(-10.f*d));
    gacc.x = fmaf(coef, h.x, gacc.x); gacc.y = fmaf(coef, h.y, gacc.y);
    gacc.z = fmaf(coef, h.z, gacc.z); gacc.w = fmaf(coef, h.w, gacc.w);
  }
  red4[w][l] = gacc;
  __syncthreads();
  if (tid < 32){
    float4 t = make_float4(0,0,0,0);
    #pragma unroll
    for (int q=0;q<8;q++){ float4 r = red4[q][tid]; t.x+=r.x; t.y+=r.y; t.z+=r.z; t.w+=r.w; }
    gfs[tid] = t;
  }
  __syncthreads();
  float4 gf = gfs[l];
  for (int i=0;i<64;i++){
    int n = b*512 + w + 8*i;
    O4[(size_t)n*64 + 32 + l] = gf;
  }
}

// ---------------- launch ----------------
extern "C" void kernel_launch(void* const* d_in, const int* in_sizes, int n_in,
                              void* d_out, int out_size){
  const float* x    = (const float*)d_in[0];
  const int*   esrc = (const int*)  d_in[1];
  const int*   edst = (const int*)  d_in[2];
  const float* W0   = (const float*)d_in[4];
  const float* b0   = (const float*)d_in[5];
  const float* Wr   = (const float*)d_in[6];
  const float* br   = (const float*)d_in[7];
  const float* gm   = (const float*)d_in[8];
  const float* bt   = (const float*)d_in[9];
  const float* Watt = (const float*)d_in[10];
  float* out = (float*)d_out;

  cudaFuncSetAttribute(k_gemm, cudaFuncAttributeMaxDynamicSharedMemorySize, GEMM_SMEM);
  cudaFuncSetAttribute(k_agg,  cudaFuncAttributeMaxDynamicSharedMemorySize, AGG_SMEM);

  k_count<<<BB, 256>>>(edst);
  k_scan <<<1, 1024>>>();
  k_fill <<<BB, 256>>>(esrc, edst);
  k_sraw0<<<NN/8, 256>>>(x, W0, b0, gm, bt);

  for (int l = 0; l < 9; l++){
    k_gemm<<<296, 256, GEMM_SMEM>>>(Wr + (size_t)l*DD*DD);
    k_agg <<<2*BB, 1024, AGG_SMEM>>>(br + (size_t)l*DD,
                                     gm + (size_t)(l+1)*DD,
                                     bt + (size_t)(l+1)*DD);
  }

  k_poolall<<<BB, 256>>>(out, Watt);
}